// round 11
// baseline (speedup 1.0000x reference)
#include <cuda_runtime.h>
#include <cuda_bf16.h>
#include <math.h>
#include <stdint.h>

#define NROWS 4096
#define DIM 512

// ---------------- descriptors ----------------
struct ERole { int enabled; int src; int e; int op; float w; };
struct GemmDesc {
  int enabled, nterms, mul;
  int srcA[3];
  int wKind[3], wIdx[3];
  int bKind, bIdx;
  int actCode;          // 0 none, 1 relu, 2 gelu
  int resBuf, dstBuf;
  float scale;
};

__device__ ERole    g_erole[8][3];
__device__ GemmDesc g_gd[8][7];
__device__ int      g_node_act[8];
__device__ float    g_node_aw[8];
__device__ int      g_rem_mask;

// ---------------- big scratch buffers ----------------
__device__ float g_outbuf[8][NROWS*DIM];
__device__ float g_qkv[3][NROWS*DIM];
__device__ float g_prep[3][NROWS*DIM];
__device__ float g_tt[3][NROWS*DIM];
__device__ float g_lnq[NROWS*DIM];
__device__ float g_attn[NROWS*DIM];

// transposed bf16 weights: [w][n*512+k], hi and lo. w: 0..33 edge, 34..65 node
__device__ __nv_bfloat16 g_Wth[66u*262144u];
__device__ __nv_bfloat16 g_Wtl[66u*262144u];

// buffer id map: 0 inpute, 1 inputo, 2..9 outbuf, 10..12 qkv, 13..15 prep, 16..18 tt, 19 lnq, 20 attn
__device__ __forceinline__ const float* bufPtrC(int id, const float* inpute, const float* inputo){
  if(id==0) return inpute;
  if(id==1) return inputo;
  if(id<10) return g_outbuf[id-2];
  if(id<13) return g_qkv[id-10];
  if(id<16) return g_prep[id-13];
  if(id<19) return g_tt[id-16];
  if(id==19) return g_lnq;
  return g_attn;
}
__device__ __forceinline__ float* bufPtrM(int id){
  if(id<10) return g_outbuf[id-2];
  if(id<13) return g_qkv[id-10];
  if(id<16) return g_prep[id-13];
  if(id<19) return g_tt[id-16];
  if(id==19) return g_lnq;
  return g_attn;
}

__device__ __forceinline__ float geluf(float x){
  float inner = 0.7978845608028654f*(x + 0.044715f*x*x*x);
  return 0.5f*x*(1.f+tanhf(inner));
}
__device__ __forceinline__ float sigmoidf(float x){ return 1.f/(1.f+expf(-x)); }

__device__ __forceinline__ float warpReduceSum(float v){
  #pragma unroll
  for(int o=16;o;o>>=1) v += __shfl_xor_sync(0xffffffffu, v, o);
  return v;
}

// ---------------- routing ----------------
__device__ void selrange(const float* p, int lo, int hi, int& sel, float& w){
  int bi=lo; float bv=p[lo];
  for(int i=lo+1;i<hi;i++) if(p[i]>bv){bv=p[i];bi=i;}
  float s=0.f;
  for(int i=lo;i<hi;i++) s += expf(p[i]-bv);
  sel=bi; w=1.f/s;
}

__device__ void fillRole(int c,int role,int sel,float w,int lind,int snode,int& processed,int computeEnabled){
  int se = sel/5, op = sel%5;
  int inn = (se==0)? -2 : snode+se;
  if(inn>=0) processed |= (1<<inn);
  int src = (inn==-2)?0 : ((inn==-1)?1 : (2+inn));
  ERole er; er.enabled=computeEnabled; er.src=src; er.e=lind+se; er.op=op; er.w=w;
  g_erole[c][role]=er;
}

__device__ void setGemm(int c,int slot,int src0,int wKind0,int wIdx0,int bKind,int bIdx,
                        int actCode,int resBuf,int dstBuf,float scale){
  GemmDesc gd;
  gd.enabled=1; gd.nterms=1; gd.mul=0;
  gd.srcA[0]=src0; gd.srcA[1]=0; gd.srcA[2]=0;
  gd.wKind[0]=wKind0; gd.wIdx[0]=wIdx0;
  gd.wKind[1]=0; gd.wIdx[1]=0; gd.wKind[2]=0; gd.wIdx[2]=0;
  gd.bKind=bKind; gd.bIdx=bIdx;
  gd.actCode=actCode; gd.resBuf=resBuf; gd.dstBuf=dstBuf; gd.scale=scale;
  g_gd[c][slot]=gd;
}

__global__ void route_kernel(const float* __restrict__ node_p, const float* __restrict__ edge_p){
  if(threadIdx.x!=0 || blockIdx.x!=0) return;
  int processed = 0;
  int lind = 0;
  for(int c=0;c<8;c++){
    for(int s=0;s<7;s++) g_gd[c][s].enabled=0;
    for(int r=0;r<3;r++) g_erole[c][r].enabled=0;

    int nsrc = (c+2<5)? c+2 : 5;
    int snode = c - nsrc;
    int L = nsrc*5;
    const float* ep0 = edge_p + lind*5;
    const float* ep1 = edge_p + 170 + lind*5;
    const float* ep2 = edge_p + 340 + lind*5;
    const float* np  = node_p + c*8;

    int act=0; { float b=np[0]; for(int i=1;i<8;i++) if(np[i]>b){b=np[i];act=i;} }
    float aw;
    { float m=np[0]; for(int i=1;i<8;i++) m=fmaxf(m,np[i]);
      float s=0.f; for(int i=0;i<8;i++) s+=expf(np[i]-m);
      aw = expf(np[act]-m)/s; }
    g_node_act[c]=act; g_node_aw[c]=aw;

    int qsel; float qw;
    selrange(ep0, 5, L, qsel, qw);
    fillRole(c,0,qsel,qw,lind,snode,processed,1);

    int ksel = -1;
    if(act<7){
      int lo = (act>0)?5:0;
      float kw;
      selrange(ep1, lo, L, ksel, kw);
      fillRole(c,1,ksel,kw,lind,snode,processed,1);
    }
    if(act<5){
      int vsel; float vw;
      if(act==0 && (ksel/5)==0){
        selrange(ep2, 0, 5, vsel, vw);
      } else {
        int lo = (act>0)?5:0;
        selrange(ep2, lo, L, vsel, vw);
      }
      fillRole(c,2,vsel,vw,lind,snode,processed,(act!=1)?1:0);
    }

    for(int r2=0;r2<3;r2++){
      ERole er = g_erole[c][r2];
      if(er.enabled && er.op!=4){
        int ac = (er.op==0)?1:((er.op==1)?2:0);
        setGemm(c, r2, 13+r2, 0, er.e, 0, er.e, ac, -1, 10+r2, er.w);
      }
    }

    int cw = c*4;
    if(act==0){
      setGemm(c,3,19,1,cw+0,1,cw+0,0,-1,16,1.f);
      setGemm(c,4,11,1,cw+1,1,cw+1,0,-1,17,1.f);
      setGemm(c,5,12,1,cw+2,1,cw+2,0,-1,18,1.f);
      setGemm(c,6,20,1,cw+3,1,cw+3,0,10,2+c,aw);
    } else if(act==1){
      setGemm(c,3,10,1,cw+0,1,cw+0,2,-1,16,1.f);
      setGemm(c,4,11,1,cw+1,1,cw+1,0,-1,17,1.f);
      setGemm(c,6,16,1,cw+3,1,cw+3,0,10,2+c,aw);
      g_gd[c][6].mul=1; g_gd[c][6].srcA[1]=17;
    } else if(act==3){
      setGemm(c,3,10,1,cw+0,-1,0,1,-1,16,1.f);
      g_gd[c][3].nterms=3;
      g_gd[c][3].srcA[1]=11; g_gd[c][3].srcA[2]=12;
      g_gd[c][3].wKind[1]=1; g_gd[c][3].wIdx[1]=cw+1;
      g_gd[c][3].wKind[2]=1; g_gd[c][3].wIdx[2]=cw+2;
      setGemm(c,6,16,1,cw+3,1,cw+3,0,10,2+c,aw);
    } else if(act==5){
      setGemm(c,3,11,1,cw+1,1,cw+1,2,-1,16,1.f);
    }

    lind += nsrc;
  }
  g_rem_mask = (~processed) & 0xFF;
}

// ---------------- weight conversion: fp32 [k][n] -> bf16 hi/lo transposed [n][k] ----------------
__global__ void convw_kernel(const float* __restrict__ eW, const float* __restrict__ nW){
  __shared__ float tile[32][33];
  int w = blockIdx.z;
  const float* src = (w<34) ? eW + (size_t)w*262144 : nW + (size_t)(w-34)*262144;
  int k0 = blockIdx.x*32, n0 = blockIdx.y*32;
  int tr = threadIdx.x>>3;
  int tc = (threadIdx.x&7)*4;
  float4 v = *(const float4*)(src + (size_t)(k0+tr)*512 + n0+tc);
  tile[tr][tc+0]=v.x; tile[tr][tc+1]=v.y; tile[tr][tc+2]=v.z; tile[tr][tc+3]=v.w;
  __syncthreads();
  int nr = threadIdx.x>>3;
  int kc = (threadIdx.x&7)*4;
  union { __nv_bfloat16 b[4]; uint2 u; } ph, pl;
  #pragma unroll
  for(int j=0;j<4;j++){
    float x = tile[kc+j][nr];
    __nv_bfloat16 h = __float2bfloat16(x);
    ph.b[j] = h;
    pl.b[j] = __float2bfloat16(x - __bfloat162float(h));
  }
  size_t off = (size_t)w*262144 + (size_t)(n0+nr)*512 + k0+kc;
  *(uint2*)(g_Wth + off) = ph.u;
  *(uint2*)(g_Wtl + off) = pl.u;
}

// ---------------- edge prep (warp-per-row) ----------------
__global__ void prep_kernel(int c, const float* __restrict__ inpute, const float* __restrict__ inputo,
                            const float* __restrict__ edge_g, const float* __restrict__ edge_beta){
  int role = blockIdx.z;
  ERole er = g_erole[c][role];
  if(!er.enabled) return;
  int wid = threadIdx.x>>5, lane = threadIdx.x&31;
  int row = blockIdx.x*8 + wid;
  const float* x = bufPtrC(er.src, inpute, inputo) + (size_t)row*DIM;
  float4 v[4];
  #pragma unroll
  for(int j=0;j<4;j++) v[j] = *(const float4*)(x + lane*4 + j*128);
  if(er.op==4){
    float* d = g_qkv[role] + (size_t)row*DIM;
    #pragma unroll
    for(int j=0;j<4;j++){
      float4 o; o.x=er.w*v[j].x; o.y=er.w*v[j].y; o.z=er.w*v[j].z; o.w=er.w*v[j].w;
      *(float4*)(d + lane*4 + j*128) = o;
    }
    return;
  }
  if(er.op==3){
    float* d = g_prep[role] + (size_t)row*DIM;
    #pragma unroll
    for(int j=0;j<4;j++) *(float4*)(d + lane*4 + j*128) = v[j];
    return;
  }
  float s=0.f;
  #pragma unroll
  for(int j=0;j<4;j++) s += v[j].x+v[j].y+v[j].z+v[j].w;
  float mean = warpReduceSum(s)*(1.f/512.f);
  float s2=0.f;
  #pragma unroll
  for(int j=0;j<4;j++){
    float a=v[j].x-mean,b=v[j].y-mean,cc=v[j].z-mean,dd=v[j].w-mean;
    s2 += a*a+b*b+cc*cc+dd*dd;
  }
  float rstd = rsqrtf(warpReduceSum(s2)*(1.f/512.f)+1e-6f);
  const float* g  = edge_g    + (size_t)er.e*DIM;
  const float* be = edge_beta + (size_t)er.e*DIM;
  float* d = g_prep[role] + (size_t)row*DIM;
  #pragma unroll
  for(int j=0;j<4;j++){
    int col = lane*4 + j*128;
    float4 gv = *(const float4*)(g+col);
    float4 bv = *(const float4*)(be+col);
    float4 o;
    o.x=(v[j].x-mean)*rstd*gv.x+bv.x; o.y=(v[j].y-mean)*rstd*gv.y+bv.y;
    o.z=(v[j].z-mean)*rstd*gv.z+bv.z; o.w=(v[j].w-mean)*rstd*gv.w+bv.w;
    *(float4*)(d+col)=o;
  }
}

// ---------------- LN(q) for MHA (warp-per-row) ----------------
__global__ void lnq_kernel(int c, const float* __restrict__ node_g, const float* __restrict__ node_beta){
  if(g_node_act[c]!=0) return;
  int wid = threadIdx.x>>5, lane = threadIdx.x&31;
  int row = blockIdx.x*8 + wid;
  const float* x = g_qkv[0] + (size_t)row*DIM;
  float4 v[4];
  #pragma unroll
  for(int j=0;j<4;j++) v[j] = *(const float4*)(x + lane*4 + j*128);
  float s=0.f;
  #pragma unroll
  for(int j=0;j<4;j++) s += v[j].x+v[j].y+v[j].z+v[j].w;
  float mean = warpReduceSum(s)*(1.f/512.f);
  float s2=0.f;
  #pragma unroll
  for(int j=0;j<4;j++){
    float a=v[j].x-mean,b=v[j].y-mean,cc=v[j].z-mean,dd=v[j].w-mean;
    s2 += a*a+b*b+cc*cc+dd*dd;
  }
  float rstd = rsqrtf(warpReduceSum(s2)*(1.f/512.f)+1e-6f);
  const float* g  = node_g    + (size_t)c*DIM;
  const float* be = node_beta + (size_t)c*DIM;
  float* d = g_lnq + (size_t)row*DIM;
  #pragma unroll
  for(int j=0;j<4;j++){
    int col = lane*4 + j*128;
    float4 gv = *(const float4*)(g+col);
    float4 bv = *(const float4*)(be+col);
    float4 o;
    o.x=(v[j].x-mean)*rstd*gv.x+bv.x; o.y=(v[j].y-mean)*rstd*gv.y+bv.y;
    o.z=(v[j].z-mean)*rstd*gv.z+bv.z; o.w=(v[j].w-mean)*rstd*gv.w+bv.w;
    *(float4*)(d+col)=o;
  }
}

// ---------------- tensor-core GEMM: ldmatrix frags + cp.async W + 2 CTA/SM ----------------
#define SMS 40
#define PART (128*SMS)      // 5120 elems
#define STG4 (4*PART)       // elems per stage (Ah,Al,Bh,Bl)

__device__ __forceinline__ void cpa16(uint32_t sdst, const void* gsrc){
  asm volatile("cp.async.cg.shared.global [%0], [%1], 16;\n" :: "r"(sdst), "l"(gsrc));
}
#define CP_COMMIT asm volatile("cp.async.commit_group;\n"::)
#define CP_WAIT(N) asm volatile("cp.async.wait_group %0;\n" :: "n"(N))

__device__ __forceinline__ void ldsm4(uint32_t& r0,uint32_t& r1,uint32_t& r2,uint32_t& r3, uint32_t saddr){
  asm volatile("ldmatrix.sync.aligned.m8n8.x4.shared.b16 {%0,%1,%2,%3}, [%4];"
    : "=r"(r0),"=r"(r1),"=r"(r2),"=r"(r3) : "r"(saddr));
}
__device__ __forceinline__ void mma16816(float* c, uint32_t a0,uint32_t a1,uint32_t a2,uint32_t a3,
                                         uint32_t b0, uint32_t b1){
  asm volatile("mma.sync.aligned.m16n8k16.row.col.f32.bf16.bf16.f32 "
    "{%0,%1,%2,%3}, {%4,%5,%6,%7}, {%8,%9}, {%0,%1,%2,%3};"
    : "+f"(c[0]),"+f"(c[1]),"+f"(c[2]),"+f"(c[3])
    : "r"(a0),"r"(a1),"r"(a2),"r"(a3),"r"(b0),"r"(b1));
}

__global__ void __launch_bounds__(256,2) gemm_kernel(int c,int slotBase,
  const float* __restrict__ inpute,const float* __restrict__ inputo,
  const float* __restrict__ edge_b,const float* __restrict__ node_b)
{
  GemmDesc gd = g_gd[c][slotBase + blockIdx.z];
  if(!gd.enabled) return;
  extern __shared__ __nv_bfloat16 sm[];

  const int rowBase = blockIdx.y*128;
  const int colBase = blockIdx.x*128;
  const int tid = threadIdx.x;
  const int lane = tid & 31;
  const int wid = tid >> 5;
  const int wr = wid >> 2;
  const int wc = wid & 3;
  const int mi = lane>>3, wi = lane&7;
  const int g8 = lane >> 2, tg = lane & 3;

  const float* Aterm[3];
  const __nv_bfloat16* Whp[3];
  const __nv_bfloat16* Wlp[3];
  #pragma unroll
  for(int t=0;t<3;t++){
    int tt = (t<gd.nterms)? t : 0;
    Aterm[t] = bufPtrC(gd.srcA[tt],inpute,inputo);
    int wg = gd.wKind[tt] ? (34+gd.wIdx[tt]) : gd.wIdx[tt];
    Whp[t] = g_Wth + (size_t)wg*262144;
    Wlp[t] = g_Wtl + (size_t)wg*262144;
  }
  const float* A2base = gd.mul ? bufPtrC(gd.srcA[1],inpute,inputo) : nullptr;

  float acc[4][4][4];
  #pragma unroll
  for(int i=0;i<4;i++)
    #pragma unroll
    for(int j=0;j<4;j++)
      #pragma unroll
      for(int q=0;q<4;q++) acc[i][j][q]=0.f;

  // A loader: rows {arL, +32, +64, +96}, 4 floats at akL
  const int arL = (tid>>3);
  const int akL = (tid&7)*4;
  // W cp.async loader: row wn, 16 bf16 at wk
  const int wn = tid>>1;
  const int wk = (tid&1)*16;

  const uint32_t smemBase = (uint32_t)__cvta_generic_to_shared(sm);
  const int chunks = gd.nterms*16;
  float4 pa[4];

  // helpers (inline)
  #define LOAD_A_REG(ch) { \
    int term_ = (ch)>>4; int k0_ = ((ch)&15)*32; \
    const float* A_ = Aterm[term_]; \
    _Pragma("unroll") \
    for(int it=0;it<4;it++){ \
      int r_ = arL + it*32; \
      pa[it] = *(const float4*)(A_ + (size_t)(rowBase+r_)*512 + k0_ + akL); \
      if(A2base){ \
        float4 u_ = *(const float4*)(A2base + (size_t)(rowBase+r_)*512 + k0_ + akL); \
        pa[it].x*=u_.x; pa[it].y*=u_.y; pa[it].z*=u_.z; pa[it].w*=u_.w; \
      } \
    } }
  #define STORE_A(st) { \
    __nv_bfloat16* Ah_ = sm + (st)*STG4; \
    __nv_bfloat16* Al_ = Ah_ + PART; \
    _Pragma("unroll") \
    for(int it=0;it<4;it++){ \
      int r_ = arL + it*32; \
      union { __nv_bfloat16 b[4]; uint2 u; } ph_, pl_; \
      float xs_[4]={pa[it].x,pa[it].y,pa[it].z,pa[it].w}; \
      _Pragma("unroll") \
      for(int j=0;j<4;j++){ \
        __nv_bfloat16 h_ = __float2bfloat16(xs_[j]); \
        ph_.b[j]=h_; pl_.b[j]=__float2bfloat16(xs_[j]-__bfloat162float(h_)); \
      } \
      *(uint2*)(Ah_ + r_*SMS + akL) = ph_.u; \
      *(uint2*)(Al_ + r_*SMS + akL) = pl_.u; \
    } }
  #define ISSUE_W(ch, st) { \
    int term_ = (ch)>>4; int k0_ = ((ch)&15)*32; \
    uint32_t dh_ = smemBase + (uint32_t)((st)*STG4 + 2*PART + wn*SMS + wk)*2; \
    uint32_t dl_ = dh_ + (uint32_t)PART*2; \
    const __nv_bfloat16* gh_ = Whp[term_] + (size_t)(colBase+wn)*512 + k0_ + wk; \
    const __nv_bfloat16* gl_ = Wlp[term_] + (size_t)(colBase+wn)*512 + k0_ + wk; \
    cpa16(dh_, gh_); cpa16(dh_+16, gh_+8); \
    cpa16(dl_, gl_); cpa16(dl_+16, gl_+8); }

  // prologue
  LOAD_A_REG(0); ISSUE_W(0,0); CP_COMMIT; STORE_A(0);
  LOAD_A_REG(1); ISSUE_W(1,1); CP_COMMIT; STORE_A(1);
  CP_WAIT(1);
  __syncthreads();

  for(int ch=0; ch<chunks; ch++){
    int st = ch&1;
    bool more = (ch+2<chunks);
    if(more){ LOAD_A_REG(ch+2); }
    // compute stage st
    {
      uint32_t aH = smemBase + (uint32_t)(st*STG4)*2;
      uint32_t aL = aH + (uint32_t)PART*2;
      uint32_t bH = aH + (uint32_t)(2*PART)*2;
      uint32_t bL = aH + (uint32_t)(3*PART)*2;
      #pragma unroll
      for(int kk=0; kk<32; kk+=16){
        uint32_t bh0[4],bh1[4],bl0[4],bl1[4];
        #pragma unroll
        for(int pr=0; pr<2; pr++){
          int n = wc*32 + pr*16 + ((mi>>1)<<3) + wi;
          uint32_t off = (uint32_t)(n*SMS + kk + ((mi&1)<<3))*2;
          uint32_t r0,r1,r2,r3;
          ldsm4(r0,r1,r2,r3, bH + off);
          bh0[2*pr]=r0; bh1[2*pr]=r1; bh0[2*pr+1]=r2; bh1[2*pr+1]=r3;
          ldsm4(r0,r1,r2,r3, bL + off);
          bl0[2*pr]=r0; bl1[2*pr]=r1; bl0[2*pr+1]=r2; bl1[2*pr+1]=r3;
        }
        #pragma unroll
        for(int mb=0; mb<4; mb++){
          int row = wr*64 + mb*16 + ((mi&1)<<3) + wi;
          uint32_t off = (uint32_t)(row*SMS + kk + ((mi>>1)<<3))*2;
          uint32_t ah0,ah1,ah2,ah3, al0,al1,al2,al3;
          ldsm4(ah0,ah1,ah2,ah3, aH + off);
          ldsm4(al0,al1,al2,al3, aL + off);
          #pragma unroll
          for(int nb=0; nb<4; nb++){
            mma16816(acc[mb][nb], ah0,ah1,ah2,ah3, bh0[nb],bh1[nb]);
            mma16816(acc[mb][nb], ah0,ah1,ah2,ah3, bl0[nb],bl1[nb]);
            mma16816(acc[mb][nb], al0,al1,al2,al3, bh0[nb],bh1[nb]);
          }
        }
      }
    }
    __syncthreads();
    if(more){
      STORE_A(st);
      ISSUE_W(ch+2, st); CP_COMMIT;
      CP_WAIT(1);
    } else {
      CP_WAIT(0);
    }
    __syncthreads();
  }

  // ---- epilogue
  const float* bias = nullptr;
  if(gd.bKind==0)      bias = edge_b + (size_t)gd.bIdx*512;
  else if(gd.bKind==1) bias = node_b + (size_t)gd.bIdx*512;
  const float* res = (gd.resBuf>=0)? bufPtrC(gd.resBuf,inpute,inputo) : nullptr;
  float* dst = bufPtrM(gd.dstBuf);
  #pragma unroll
  for(int mb=0;mb<4;mb++){
    #pragma unroll
    for(int nb=0;nb<4;nb++){
      int row0 = rowBase + wr*64 + mb*16 + g8;
      int col0 = colBase + wc*32 + nb*8 + tg*2;
      #pragma unroll
      for(int half=0; half<2; half++){
        int row = row0 + half*8;
        float z0 = acc[mb][nb][half*2+0] + (bias? bias[col0]:0.f);
        float z1 = acc[mb][nb][half*2+1] + (bias? bias[col0+1]:0.f);
        if(gd.actCode==1){ z0=fmaxf(z0,0.f); z1=fmaxf(z1,0.f); }
        else if(gd.actCode==2){ z0=geluf(z0); z1=geluf(z1); }
        if(res){
          float2 rv = *(const float2*)(res + (size_t)row*512 + col0);
          z0 += rv.x; z1 += rv.y;
        }
        float2 ov; ov.x = gd.scale*z0; ov.y = gd.scale*z1;
        *(float2*)(dst + (size_t)row*512 + col0) = ov;
      }
    }
  }
}

// ---------------- tensor-core flash attention (unchanged from R6 passing version) ----------------
#define ASROW 72
#define AQ_H 0
#define AQ_L 9216
#define AK_H 18432
#define AK_L 23040
#define AV_H 27648
#define AV_L 32256
#define ATTN_SMEM_ELEMS 36864

__device__ __forceinline__ void ldsm4t(uint32_t& r0,uint32_t& r1,uint32_t& r2,uint32_t& r3, uint32_t saddr){
  asm volatile("ldmatrix.sync.aligned.m8n8.x4.trans.shared.b16 {%0,%1,%2,%3}, [%4];"
    : "=r"(r0),"=r"(r1),"=r"(r2),"=r"(r3) : "r"(saddr));
}
__device__ __forceinline__ void split2(float a, float b, uint32_t& hi, uint32_t& lo){
  __nv_bfloat16 ha=__float2bfloat16(a), hb=__float2bfloat16(b);
  __nv_bfloat162 hh; hh.x=ha; hh.y=hb; hi = *(uint32_t*)&hh;
  __nv_bfloat162 ll; ll.x=__float2bfloat16(a-__bfloat162float(ha));
  ll.y=__float2bfloat16(b-__bfloat162float(hb)); lo = *(uint32_t*)&ll;
}

__global__ void __launch_bounds__(256,1) attn_kernel(int c){
  if(g_node_act[c]!=0) return;
  extern __shared__ __nv_bfloat16 asm_[];
  const int tid = threadIdx.x;
  const int lane = tid & 31;
  const int wid = tid >> 5;
  const int mi = lane>>3, wi = lane&7;
  const int g8 = lane>>2, tg = lane&3;
  const int bh = blockIdx.y; const int b = bh>>3, h = bh&7;
  const int q0 = blockIdx.x*128;
  const float* Q = g_tt[0]; const float* K = g_tt[1]; const float* V = g_tt[2];
  const uint32_t smemBase = (uint32_t)__cvta_generic_to_shared(asm_);

  {
    int row = tid>>1;
    int col0 = (tid&1)*32;
    const float* src = Q + ((size_t)(b*1024+q0+row))*DIM + h*64 + col0;
    #pragma unroll
    for(int j=0;j<8;j++){
      float4 v = *(const float4*)(src + j*4);
      uint32_t h0,l0,h1,l1;
      split2(v.x,v.y,h0,l0); split2(v.z,v.w,h1,l1);
      int o = row*ASROW + col0 + j*4;
      *(uint32_t*)(asm_+AQ_H+o)   = h0; *(uint32_t*)(asm_+AQ_H+o+2) = h1;
      *(uint32_t*)(asm_+AQ_L+o)   = l0; *(uint32_t*)(asm_+AQ_L+o+2) = l1;
    }
  }
  __syncthreads();

  uint32_t qh[4][4], ql[4][4];
  {
    int row = wid*16 + ((mi&1)<<3) + wi;
    #pragma unroll
    for(int ks=0;ks<4;ks++){
      uint32_t off = (uint32_t)(row*ASROW + ks*16 + ((mi>>1)<<3))*2;
      ldsm4(qh[ks][0],qh[ks][1],qh[ks][2],qh[ks][3], smemBase + AQ_H*2 + off);
      ldsm4(ql[ks][0],ql[ks][1],ql[ks][2],ql[ks][3], smemBase + AQ_L*2 + off);
    }
  }

  float o_acc[8][4];
  #pragma unroll
  for(int nb=0;nb<8;nb++)
    #pragma unroll
    for(int q=0;q<4;q++) o_acc[nb][q]=0.f;
  float m_st[2] = {-1e30f,-1e30f};
  float l_st[2] = {0.f,0.f};

  for(int chunk=0; chunk<16; chunk++){
    __syncthreads();
    {
      int key = tid>>2;
      int col0 = (tid&3)*16;
      size_t base = ((size_t)(b*1024 + chunk*64 + key))*DIM + h*64 + col0;
      #pragma unroll
      for(int j=0;j<4;j++){
        float4 kv = *(const float4*)(K + base + j*4);
        float4 vv = *(const float4*)(V + base + j*4);
        uint32_t h0,l0,h1,l1;
        int o = key*ASROW + col0 + j*4;
        split2(kv.x,kv.y,h0,l0); split2(kv.z,kv.w,h1,l1);
        *(uint32_t*)(asm_+AK_H+o) = h0; *(uint32_t*)(asm_+AK_H+o+2) = h1;
        *(uint32_t*)(asm_+AK_L+o) = l0; *(uint32_t*)(asm_+AK_L+o+2) = l1;
        split2(vv.x,vv.y,h0,l0); split2(vv.z,vv.w,h1,l1);
        *(uint32_t*)(asm_+AV_H+o) = h0; *(uint32_t*)(asm_+AV_H+o+2) = h1;
        *(uint32_t*)(asm_+AV_L+o) = l0; *(uint32_t*)(asm_+AV_L+o+2) = l1;
      }
    }
    __syncthreads();

    float s[8][4];
    #pragma unroll
    for(int nb=0;nb<8;nb++)
      #pragma unroll
      for(int q=0;q<4;q++) s[nb][q]=0.f;
    #pragma unroll
    for(int ks=0;ks<4;ks++){
      uint32_t kb0[8], kb1[8], klo0[8], klo1[8];
      #pragma unroll
      for(int pr=0;pr<4;pr++){
        int n = pr*16 + ((mi>>1)<<3) + wi;
        uint32_t off = (uint32_t)(n*ASROW + ks*16 + ((mi&1)<<3))*2;
        uint32_t r0,r1,r2,r3;
        ldsm4(r0,r1,r2,r3, smemBase + AK_H*2 + off);
        kb0[2*pr]=r0; kb1[2*pr]=r1; kb0[2*pr+1]=r2; kb1[2*pr+1]=r3;
        ldsm4(r0,r1,r2,r3, smemBase + AK_L*2 + off);
        klo0[2*pr]=r0; klo1[2*pr]=r1; klo0[2*pr+1]=r2; klo1[2*pr+1]=r3;
      }
      #pragma unroll
      for(int nb=0;nb<8;nb++){
        mma16816(s[nb], qh[ks][0],qh[ks][1],qh[ks][2],qh[ks][3], kb0[nb],kb1[nb]);
        mma16816(s[nb], qh[ks][0],qh[ks][1],qh[ks][2],qh[ks][3], klo0[nb],klo1[nb]);
        mma16816(s[nb], ql[ks][0],ql[ks][1],ql[ks][2],ql[ks][3], kb0[nb],kb1[nb]);
      }
    }

    float p[8][4];
    #pragma unroll
    for(int hr=0;hr<2;hr++){
      float mloc = -1e30f;
      #pragma unroll
      for(int nb=0;nb<8;nb++){
        float a = s[nb][hr*2+0]*0.125f, bb = s[nb][hr*2+1]*0.125f;
        s[nb][hr*2+0]=a; s[nb][hr*2+1]=bb;
        mloc = fmaxf(mloc, fmaxf(a,bb));
      }
      mloc = fmaxf(mloc, __shfl_xor_sync(0xffffffffu, mloc, 1));
      mloc = fmaxf(mloc, __shfl_xor_sync(0xffffffffu, mloc, 2));
      float m_new = fmaxf(m_st[hr], mloc);
      float corr = __expf(m_st[hr]-m_new);
      float lloc = 0.f;
      #pragma unroll
      for(int nb=0;nb<8;nb++){
        float p0 = __expf(s[nb][hr*2+0]-m_new);
        float p1 = __expf(s[nb][hr*2+1]-m_new);
        p[nb][hr*2+0]=p0; p[nb][hr*2+1]=p1;
        lloc += p0+p1;
      }
      lloc += __shfl_xor_sync(0xffffffffu, lloc, 1);
      lloc += __shfl_xor_sync(0xffffffffu, lloc, 2);
      l_st[hr] = l_st[hr]*corr + lloc;
      m_st[hr] = m_new;
      #pragma unroll
      for(int nb=0;nb<8;nb++){ o_acc[nb][hr*2+0]*=corr; o_acc[nb][hr*2+1]*=corr; }
    }

    #pragma unroll
    for(int ks=0;ks<4;ks++){
      uint32_t pa0,pa1,pa2,pa3, pl0,pl1,pl2,pl3;
      split2(p[2*ks][0],   p[2*ks][1],   pa0, pl0);
      split2(p[2*ks][2],   p[2*ks][3],   pa1, pl1);
      split2(p[2*ks+1][0], p[2*ks+1][1], pa2, pl2);
      split2(p[2*ks+1][2], p[2*ks+1][3], pa3, pl3);
      #pragma unroll
      for(int pr=0;pr<4;pr++){
        int key = ks*16 + ((mi&1)<<3) + wi;
        int d0  = pr*16 + ((mi>>1)<<3);
        uint32_t off = (uint32_t)(key*ASROW + d0)*2;
        uint32_t vh0,vh1,vh2,vh3, vl0,vl1,vl2,vl3;
        ldsm4t(vh0,vh1,vh2,vh3, smemBase + AV_H*2 + off);
        ldsm4t(vl0,vl1,vl2,vl3, smemBase + AV_L*2 + off);
        mma16816(o_acc[2*pr],   pa0,pa1,pa2,pa3, vh0,vh1);
        mma16816(o_acc[2*pr],   pa0,pa1,pa2,pa3, vl0,vl1);
        mma16816(o_acc[2*pr],   pl0,pl1,pl2,pl3, vh0,vh1);
        mma16816(o_acc[2*pr+1], pa0,pa1,pa2,pa3, vh2,vh3);
        mma16816(o_acc[2*pr+1], pa0,pa1,pa2,pa3, vl2,vl3);
        mma16816(o_acc[2*pr+1], pl0,pl1,pl2,pl3, vh2,vh3);
      }
    }
  }

  #pragma unroll
  for(int hr=0;hr<2;hr++){
    float inv = 1.f/l_st[hr];
    int row = q0 + wid*16 + hr*8 + g8;
    #pragma unroll
    for(int nb=0;nb<8;nb++){
      int col = h*64 + nb*8 + tg*2;
      float2 ov; ov.x = o_acc[nb][hr*2+0]*inv; ov.y = o_acc[nb][hr*2+1]*inv;
      *(float2*)(g_attn + ((size_t)(b*1024+row))*DIM + col) = ov;
    }
  }
}

// ---------------- elementwise node ops (warp-per-row) ----------------
__global__ void post_elt(int c, const float* __restrict__ node_g, const float* __restrict__ node_beta){
  int act = g_node_act[c];
  if(act==0||act==1||act==3) return;
  float aw = g_node_aw[c];
  int wid = threadIdx.x>>5, lane = threadIdx.x&31;
  int row = blockIdx.x*8 + wid;
  size_t off=(size_t)row*DIM;
  const float* q=g_qkv[0]+off; const float* k=g_qkv[1]+off; const float* v=g_qkv[2]+off;
  float* o = g_outbuf[c]+off;
  if(act==4||act==5||act==6){
    #pragma unroll
    for(int j=0;j<4;j++){
      int col = lane*4 + j*128;
      float4 qv = *(const float4*)(q+col);
      float4 ov;
      if(act==4){
        float4 kv = *(const float4*)(k+col);
        float4 vv = *(const float4*)(v+col);
        ov.x=aw*(qv.x*sigmoidf(kv.x)+vv.x); ov.y=aw*(qv.y*sigmoidf(kv.y)+vv.y);
        ov.z=aw*(qv.z*sigmoidf(kv.z)+vv.z); ov.w=aw*(qv.w*sigmoidf(kv.w)+vv.w);
      } else if(act==5){
        float4 tv = *(const float4*)(g_tt[0]+off+col);
        ov.x=aw*(qv.x+tv.x); ov.y=aw*(qv.y+tv.y); ov.z=aw*(qv.z+tv.z); ov.w=aw*(qv.w+tv.w);
      } else {
        float4 kv = *(const float4*)(k+col);
        ov.x=aw*(qv.x+kv.x); ov.y=aw*(qv.y+kv.y); ov.z=aw*(qv.z+kv.z); ov.w=aw*(qv.w+kv.w);
      }
      *(float4*)(o+col)=ov;
    }
    return;
  }
  float4 x[4];
  #pragma unroll
  for(int j=0;j<4;j++){
    int col = lane*4 + j*128;
    float4 qv = *(const float4*)(q+col);
    if(act==2){
      float4 kv = *(const float4*)(k+col);
      float4 vv = *(const float4*)(v+col);
      qv.x+=kv.x+vv.x; qv.y+=kv.y+vv.y; qv.z+=kv.z+vv.z; qv.w+=kv.w+vv.w;
    }
    x[j]=qv;
  }
  float s=0.f;
  #pragma unroll
  for(int j=0;j<4;j++) s += x[j].x+x[j].y+x[j].z+x[j].w;
  float mean = warpReduceSum(s)*(1.f/512.f);
  float s2=0.f;
  #pragma unroll
  for(int j=0;j<4;j++){
    float a=x[j].x-mean,b=x[j].y-mean,cc=x[j].z-mean,dd=x[j].w-mean;
    s2 += a*a+b*b+cc*cc+dd*dd;
  }
  float rstd = rsqrtf(warpReduceSum(s2)*(1.f/512.f)+1e-6f);
  const float* g  = node_g    + (size_t)c*DIM;
  const float* be = node_beta + (size_t)c*DIM;
  #pragma unroll
  for(int j=0;j<4;j++){
    int col = lane*4 + j*128;
    float4 gv = *(const float4*)(g+col);
    float4 bv = *(const float4*)(be+col);
    float4 ov;
    ov.x=aw*((x[j].x-mean)*rstd*gv.x+bv.x); ov.y=aw*((x[j].y-mean)*rstd*gv.y+bv.y);
    ov.z=aw*((x[j].z-mean)*rstd*gv.z+bv.z); ov.w=aw*((x[j].w-mean)*rstd*gv.w+bv.w);
    *(float4*)(o+col)=ov;
  }
}

// ---------------- final: sum remaining nodes + LN (warp-per-row) ----------------
__global__ void final_kernel(const float* __restrict__ og, const float* __restrict__ obe, float* __restrict__ out){
  int wid = threadIdx.x>>5, lane = threadIdx.x&31;
  int row = blockIdx.x*8 + wid;
  int mask = g_rem_mask;
  size_t off=(size_t)row*DIM;
  float4 x[4];
  #pragma unroll
  for(int j=0;j<4;j++){ x[j].x=0;x[j].y=0;x[j].z=0;x[j].w=0; }
  #pragma unroll
  for(int i=0;i<8;i++) if((mask>>i)&1){
    #pragma unroll
    for(int j=0;j<4;j++){
      float4 v = *(const float4*)(g_outbuf[i]+off+lane*4+j*128);
      x[j].x+=v.x; x[j].y+=v.y; x[j].z+=v.z; x[j].w+=v.w;
    }
  }
  float s=0.f;
  #pragma unroll
  for(int j=0;j<4;j++) s += x[j].x+x[j].y+x[j].z+x[j].w;
  float mean = warpReduceSum(s)*(1.f/512.f);
  float s2=0.f;
  #pragma unroll
  for(int j=0;j<4;j++){
    float a=x[j].x-mean,b=x[j].y-mean,cc=x[j].z-mean,dd=x[j].w-mean;
    s2 += a*a+b*b+cc*cc+dd*dd;
  }
  float rstd = rsqrtf(warpReduceSum(s2)*(1.f/512.f)+1e-6f);
  #pragma unroll
  for(int j=0;j<4;j++){
    int col = lane*4 + j*128;
    float4 gv = *(const float4*)(og+col);
    float4 bv = *(const float4*)(obe+col);
    float4 ov;
    ov.x=(x[j].x-mean)*rstd*gv.x+bv.x; ov.y=(x[j].y-mean)*rstd*gv.y+bv.y;
    ov.z=(x[j].z-mean)*rstd*gv.z+bv.z; ov.w=(x[j].w-mean)*rstd*gv.w+bv.w;
    *(float4*)(out+off+col)=ov;
  }
}

extern "C" void kernel_launch(void* const* d_in, const int* in_sizes, int n_in,
                              void* d_out, int out_size) {
  (void)in_sizes; (void)n_in; (void)out_size;
  const float* inpute    = (const float*)d_in[0];
  const float* inputo    = (const float*)d_in[1];
  const float* node_p    = (const float*)d_in[2];
  const float* edge_p    = (const float*)d_in[3];
  const float* edge_W    = (const float*)d_in[4];
  const float* edge_b    = (const float*)d_in[5];
  const float* edge_g    = (const float*)d_in[6];
  const float* edge_beta = (const float*)d_in[7];
  const float* node_W    = (const float*)d_in[8];
  const float* node_b    = (const float*)d_in[9];
  const float* node_g    = (const float*)d_in[10];
  const float* node_beta = (const float*)d_in[11];
  const float* out_g     = (const float*)d_in[12];
  const float* out_beta  = (const float*)d_in[13];
  float* out = (float*)d_out;

  const int gemmSmem = 2*STG4*(int)sizeof(__nv_bfloat16); // 81920 bytes
  cudaFuncSetAttribute(gemm_kernel, cudaFuncAttributeMaxDynamicSharedMemorySize, gemmSmem);
  const int attnSmem = ATTN_SMEM_ELEMS*(int)sizeof(__nv_bfloat16); // 73728 bytes
  cudaFuncSetAttribute(attn_kernel, cudaFuncAttributeMaxDynamicSharedMemorySize, attnSmem);

  route_kernel<<<1,1>>>(node_p, edge_p);
  convw_kernel<<<dim3(16,16,66),256>>>(edge_W, node_W);
  for(int c=0;c<8;c++){
    prep_kernel<<<dim3(512,1,3),256>>>(c, inpute, inputo, edge_g, edge_beta);
    gemm_kernel<<<dim3(4,32,3),256,gemmSmem>>>(c,0,inpute,inputo,edge_b,node_b);
    lnq_kernel<<<512,256>>>(c, node_g, node_beta);
    gemm_kernel<<<dim3(4,32,3),256,gemmSmem>>>(c,3,inpute,inputo,edge_b,node_b);
    attn_kernel<<<dim3(8,32),256,attnSmem>>>(c);
    gemm_kernel<<<dim3(4,32,1),256,gemmSmem>>>(c,6,inpute,inputo,edge_b,node_b);
    post_elt<<<512,256>>>(c, node_g, node_beta);
  }
  final_kernel<<<512,256>>>(out_g, out_beta, out);
}

// round 12
// speedup vs baseline: 1.1565x; 1.1565x over previous
#include <cuda_runtime.h>
#include <cuda_bf16.h>
#include <math.h>
#include <stdint.h>

#define NROWS 4096
#define DIM 512

// ---------------- descriptors ----------------
struct ERole { int enabled; int src; int e; int op; float w; };
struct GemmDesc {
  int enabled, nterms, mul;
  int srcA[3];
  int wKind[3], wIdx[3];
  int bKind, bIdx;
  int actCode;          // 0 none, 1 relu, 2 gelu
  int resBuf, dstBuf;
  float scale;
};

__device__ ERole    g_erole[8][3];
__device__ GemmDesc g_gd[8][7];
__device__ int      g_node_act[8];
__device__ float    g_node_aw[8];
__device__ int      g_rem_mask;

// ---------------- big scratch buffers ----------------
__device__ float g_outbuf[8][NROWS*DIM];
__device__ float g_qkv[3][NROWS*DIM];
__device__ float g_prep[3][NROWS*DIM];
__device__ float g_tt[3][NROWS*DIM];
__device__ float g_lnq[NROWS*DIM];
__device__ float g_attn[NROWS*DIM];

// transposed bf16 weights: [w][n*512+k], hi and lo. w: 0..33 edge, 34..65 node
__device__ __nv_bfloat16 g_Wth[66u*262144u];
__device__ __nv_bfloat16 g_Wtl[66u*262144u];

// buffer id map: 0 inpute, 1 inputo, 2..9 outbuf, 10..12 qkv, 13..15 prep, 16..18 tt, 19 lnq, 20 attn
__device__ __forceinline__ const float* bufPtrC(int id, const float* inpute, const float* inputo){
  if(id==0) return inpute;
  if(id==1) return inputo;
  if(id<10) return g_outbuf[id-2];
  if(id<13) return g_qkv[id-10];
  if(id<16) return g_prep[id-13];
  if(id<19) return g_tt[id-16];
  if(id==19) return g_lnq;
  return g_attn;
}
__device__ __forceinline__ float* bufPtrM(int id){
  if(id<10) return g_outbuf[id-2];
  if(id<13) return g_qkv[id-10];
  if(id<16) return g_prep[id-13];
  if(id<19) return g_tt[id-16];
  if(id==19) return g_lnq;
  return g_attn;
}

__device__ __forceinline__ float geluf(float x){
  float inner = 0.7978845608028654f*(x + 0.044715f*x*x*x);
  return 0.5f*x*(1.f+tanhf(inner));
}
__device__ __forceinline__ float sigmoidf(float x){ return 1.f/(1.f+expf(-x)); }

__device__ __forceinline__ float warpReduceSum(float v){
  #pragma unroll
  for(int o=16;o;o>>=1) v += __shfl_xor_sync(0xffffffffu, v, o);
  return v;
}

// ---------------- routing ----------------
__device__ void selrange(const float* p, int lo, int hi, int& sel, float& w){
  int bi=lo; float bv=p[lo];
  for(int i=lo+1;i<hi;i++) if(p[i]>bv){bv=p[i];bi=i;}
  float s=0.f;
  for(int i=lo;i<hi;i++) s += expf(p[i]-bv);
  sel=bi; w=1.f/s;
}

__device__ void fillRole(int c,int role,int sel,float w,int lind,int snode,int& processed,int computeEnabled){
  int se = sel/5, op = sel%5;
  int inn = (se==0)? -2 : snode+se;
  if(inn>=0) processed |= (1<<inn);
  int src = (inn==-2)?0 : ((inn==-1)?1 : (2+inn));
  ERole er; er.enabled=computeEnabled; er.src=src; er.e=lind+se; er.op=op; er.w=w;
  g_erole[c][role]=er;
}

__device__ void setGemm(int c,int slot,int src0,int wKind0,int wIdx0,int bKind,int bIdx,
                        int actCode,int resBuf,int dstBuf,float scale){
  GemmDesc gd;
  gd.enabled=1; gd.nterms=1; gd.mul=0;
  gd.srcA[0]=src0; gd.srcA[1]=0; gd.srcA[2]=0;
  gd.wKind[0]=wKind0; gd.wIdx[0]=wIdx0;
  gd.wKind[1]=0; gd.wIdx[1]=0; gd.wKind[2]=0; gd.wIdx[2]=0;
  gd.bKind=bKind; gd.bIdx=bIdx;
  gd.actCode=actCode; gd.resBuf=resBuf; gd.dstBuf=dstBuf; gd.scale=scale;
  g_gd[c][slot]=gd;
}

__global__ void route_kernel(const float* __restrict__ node_p, const float* __restrict__ edge_p){
  if(threadIdx.x!=0 || blockIdx.x!=0) return;
  int processed = 0;
  int lind = 0;
  for(int c=0;c<8;c++){
    for(int s=0;s<7;s++) g_gd[c][s].enabled=0;
    for(int r=0;r<3;r++) g_erole[c][r].enabled=0;

    int nsrc = (c+2<5)? c+2 : 5;
    int snode = c - nsrc;
    int L = nsrc*5;
    const float* ep0 = edge_p + lind*5;
    const float* ep1 = edge_p + 170 + lind*5;
    const float* ep2 = edge_p + 340 + lind*5;
    const float* np  = node_p + c*8;

    int act=0; { float b=np[0]; for(int i=1;i<8;i++) if(np[i]>b){b=np[i];act=i;} }
    float aw;
    { float m=np[0]; for(int i=1;i<8;i++) m=fmaxf(m,np[i]);
      float s=0.f; for(int i=0;i<8;i++) s+=expf(np[i]-m);
      aw = expf(np[act]-m)/s; }
    g_node_act[c]=act; g_node_aw[c]=aw;

    int qsel; float qw;
    selrange(ep0, 5, L, qsel, qw);
    fillRole(c,0,qsel,qw,lind,snode,processed,1);

    int ksel = -1;
    if(act<7){
      int lo = (act>0)?5:0;
      float kw;
      selrange(ep1, lo, L, ksel, kw);
      fillRole(c,1,ksel,kw,lind,snode,processed,1);
    }
    if(act<5){
      int vsel; float vw;
      if(act==0 && (ksel/5)==0){
        selrange(ep2, 0, 5, vsel, vw);
      } else {
        int lo = (act>0)?5:0;
        selrange(ep2, lo, L, vsel, vw);
      }
      fillRole(c,2,vsel,vw,lind,snode,processed,(act!=1)?1:0);
    }

    for(int r2=0;r2<3;r2++){
      ERole er = g_erole[c][r2];
      if(er.enabled && er.op!=4){
        int ac = (er.op==0)?1:((er.op==1)?2:0);
        setGemm(c, r2, 13+r2, 0, er.e, 0, er.e, ac, -1, 10+r2, er.w);
      }
    }

    int cw = c*4;
    if(act==0){
      setGemm(c,3,19,1,cw+0,1,cw+0,0,-1,16,1.f);
      setGemm(c,4,11,1,cw+1,1,cw+1,0,-1,17,1.f);
      setGemm(c,5,12,1,cw+2,1,cw+2,0,-1,18,1.f);
      setGemm(c,6,20,1,cw+3,1,cw+3,0,10,2+c,aw);
    } else if(act==1){
      setGemm(c,3,10,1,cw+0,1,cw+0,2,-1,16,1.f);
      setGemm(c,4,11,1,cw+1,1,cw+1,0,-1,17,1.f);
      setGemm(c,6,16,1,cw+3,1,cw+3,0,10,2+c,aw);
      g_gd[c][6].mul=1; g_gd[c][6].srcA[1]=17;
    } else if(act==3){
      setGemm(c,3,10,1,cw+0,-1,0,1,-1,16,1.f);
      g_gd[c][3].nterms=3;
      g_gd[c][3].srcA[1]=11; g_gd[c][3].srcA[2]=12;
      g_gd[c][3].wKind[1]=1; g_gd[c][3].wIdx[1]=cw+1;
      g_gd[c][3].wKind[2]=1; g_gd[c][3].wIdx[2]=cw+2;
      setGemm(c,6,16,1,cw+3,1,cw+3,0,10,2+c,aw);
    } else if(act==5){
      setGemm(c,3,11,1,cw+1,1,cw+1,2,-1,16,1.f);
    }

    lind += nsrc;
  }
  g_rem_mask = (~processed) & 0xFF;
}

// ---------------- weight conversion: fp32 [k][n] -> bf16 hi/lo transposed [n][k] ----------------
__global__ void convw_kernel(const float* __restrict__ eW, const float* __restrict__ nW){
  __shared__ float tile[32][33];
  int w = blockIdx.z;
  const float* src = (w<34) ? eW + (size_t)w*262144 : nW + (size_t)(w-34)*262144;
  int k0 = blockIdx.x*32, n0 = blockIdx.y*32;
  int tr = threadIdx.x>>3;
  int tc = (threadIdx.x&7)*4;
  float4 v = *(const float4*)(src + (size_t)(k0+tr)*512 + n0+tc);
  tile[tr][tc+0]=v.x; tile[tr][tc+1]=v.y; tile[tr][tc+2]=v.z; tile[tr][tc+3]=v.w;
  __syncthreads();
  int nr = threadIdx.x>>3;
  int kc = (threadIdx.x&7)*4;
  union { __nv_bfloat16 b[4]; uint2 u; } ph, pl;
  #pragma unroll
  for(int j=0;j<4;j++){
    float x = tile[kc+j][nr];
    __nv_bfloat16 h = __float2bfloat16(x);
    ph.b[j] = h;
    pl.b[j] = __float2bfloat16(x - __bfloat162float(h));
  }
  size_t off = (size_t)w*262144 + (size_t)(n0+nr)*512 + k0+kc;
  *(uint2*)(g_Wth + off) = ph.u;
  *(uint2*)(g_Wtl + off) = pl.u;
}

// ---------------- edge prep (warp-per-row) ----------------
__global__ void prep_kernel(int c, const float* __restrict__ inpute, const float* __restrict__ inputo,
                            const float* __restrict__ edge_g, const float* __restrict__ edge_beta){
  int role = blockIdx.z;
  ERole er = g_erole[c][role];
  if(!er.enabled) return;
  int wid = threadIdx.x>>5, lane = threadIdx.x&31;
  int row = blockIdx.x*8 + wid;
  const float* x = bufPtrC(er.src, inpute, inputo) + (size_t)row*DIM;
  float4 v[4];
  #pragma unroll
  for(int j=0;j<4;j++) v[j] = *(const float4*)(x + lane*4 + j*128);
  if(er.op==4){
    float* d = g_qkv[role] + (size_t)row*DIM;
    #pragma unroll
    for(int j=0;j<4;j++){
      float4 o; o.x=er.w*v[j].x; o.y=er.w*v[j].y; o.z=er.w*v[j].z; o.w=er.w*v[j].w;
      *(float4*)(d + lane*4 + j*128) = o;
    }
    return;
  }
  if(er.op==3){
    float* d = g_prep[role] + (size_t)row*DIM;
    #pragma unroll
    for(int j=0;j<4;j++) *(float4*)(d + lane*4 + j*128) = v[j];
    return;
  }
  float s=0.f;
  #pragma unroll
  for(int j=0;j<4;j++) s += v[j].x+v[j].y+v[j].z+v[j].w;
  float mean = warpReduceSum(s)*(1.f/512.f);
  float s2=0.f;
  #pragma unroll
  for(int j=0;j<4;j++){
    float a=v[j].x-mean,b=v[j].y-mean,cc=v[j].z-mean,dd=v[j].w-mean;
    s2 += a*a+b*b+cc*cc+dd*dd;
  }
  float rstd = rsqrtf(warpReduceSum(s2)*(1.f/512.f)+1e-6f);
  const float* g  = edge_g    + (size_t)er.e*DIM;
  const float* be = edge_beta + (size_t)er.e*DIM;
  float* d = g_prep[role] + (size_t)row*DIM;
  #pragma unroll
  for(int j=0;j<4;j++){
    int col = lane*4 + j*128;
    float4 gv = *(const float4*)(g+col);
    float4 bv = *(const float4*)(be+col);
    float4 o;
    o.x=(v[j].x-mean)*rstd*gv.x+bv.x; o.y=(v[j].y-mean)*rstd*gv.y+bv.y;
    o.z=(v[j].z-mean)*rstd*gv.z+bv.z; o.w=(v[j].w-mean)*rstd*gv.w+bv.w;
    *(float4*)(d+col)=o;
  }
}

// ---------------- LN(q) for MHA (warp-per-row) ----------------
__global__ void lnq_kernel(int c, const float* __restrict__ node_g, const float* __restrict__ node_beta){
  if(g_node_act[c]!=0) return;
  int wid = threadIdx.x>>5, lane = threadIdx.x&31;
  int row = blockIdx.x*8 + wid;
  const float* x = g_qkv[0] + (size_t)row*DIM;
  float4 v[4];
  #pragma unroll
  for(int j=0;j<4;j++) v[j] = *(const float4*)(x + lane*4 + j*128);
  float s=0.f;
  #pragma unroll
  for(int j=0;j<4;j++) s += v[j].x+v[j].y+v[j].z+v[j].w;
  float mean = warpReduceSum(s)*(1.f/512.f);
  float s2=0.f;
  #pragma unroll
  for(int j=0;j<4;j++){
    float a=v[j].x-mean,b=v[j].y-mean,cc=v[j].z-mean,dd=v[j].w-mean;
    s2 += a*a+b*b+cc*cc+dd*dd;
  }
  float rstd = rsqrtf(warpReduceSum(s2)*(1.f/512.f)+1e-6f);
  const float* g  = node_g    + (size_t)c*DIM;
  const float* be = node_beta + (size_t)c*DIM;
  float* d = g_lnq + (size_t)row*DIM;
  #pragma unroll
  for(int j=0;j<4;j++){
    int col = lane*4 + j*128;
    float4 gv = *(const float4*)(g+col);
    float4 bv = *(const float4*)(be+col);
    float4 o;
    o.x=(v[j].x-mean)*rstd*gv.x+bv.x; o.y=(v[j].y-mean)*rstd*gv.y+bv.y;
    o.z=(v[j].z-mean)*rstd*gv.z+bv.z; o.w=(v[j].w-mean)*rstd*gv.w+bv.w;
    *(float4*)(d+col)=o;
  }
}

// ---------------- tensor-core GEMM: 128x64 tile, register staging, 2 CTA/SM ----------------
#define SMS 40
#define PART_A (128*SMS)    // 5120 elems
#define PART_B (64*SMS)     // 2560 elems
#define STG (2*PART_A + 2*PART_B)  // 15360 elems per stage

__device__ __forceinline__ void ldsm4(uint32_t& r0,uint32_t& r1,uint32_t& r2,uint32_t& r3, uint32_t saddr){
  asm volatile("ldmatrix.sync.aligned.m8n8.x4.shared.b16 {%0,%1,%2,%3}, [%4];"
    : "=r"(r0),"=r"(r1),"=r"(r2),"=r"(r3) : "r"(saddr));
}
__device__ __forceinline__ void mma16816(float* c, uint32_t a0,uint32_t a1,uint32_t a2,uint32_t a3,
                                         uint32_t b0, uint32_t b1){
  asm volatile("mma.sync.aligned.m16n8k16.row.col.f32.bf16.bf16.f32 "
    "{%0,%1,%2,%3}, {%4,%5,%6,%7}, {%8,%9}, {%0,%1,%2,%3};"
    : "+f"(c[0]),"+f"(c[1]),"+f"(c[2]),"+f"(c[3])
    : "r"(a0),"r"(a1),"r"(a2),"r"(a3),"r"(b0),"r"(b1));
}

__global__ void __launch_bounds__(256,2) gemm_kernel(int c,int slotBase,
  const float* __restrict__ inpute,const float* __restrict__ inputo,
  const float* __restrict__ edge_b,const float* __restrict__ node_b)
{
  GemmDesc gd = g_gd[c][slotBase + blockIdx.z];
  if(!gd.enabled) return;
  extern __shared__ __nv_bfloat16 sm[];
  // stage layout: Ah | Al | Bh | Bl
  const int rowBase = blockIdx.y*128;
  const int colBase = blockIdx.x*64;
  const int tid = threadIdx.x;
  const int lane = tid & 31;
  const int wid = tid >> 5;
  const int wr = wid >> 1;       // 0..3 : 32-row group
  const int wc = wid & 1;        // 0..1 : 32-col group
  const int mi = lane>>3, wi = lane&7;
  const int g8 = lane >> 2, tg = lane & 3;

  const float* Aterm[3];
  const __nv_bfloat16* Whp[3];
  const __nv_bfloat16* Wlp[3];
  for(int t=0;t<gd.nterms;t++){
    Aterm[t] = bufPtrC(gd.srcA[t],inpute,inputo);
    int wg = gd.wKind[t] ? (34+gd.wIdx[t]) : gd.wIdx[t];
    Whp[t] = g_Wth + (size_t)wg*262144;
    Wlp[t] = g_Wtl + (size_t)wg*262144;
  }
  const float* A2base = gd.mul ? bufPtrC(gd.srcA[1],inpute,inputo) : nullptr;

  float acc[2][4][4];
  #pragma unroll
  for(int i=0;i<2;i++)
    #pragma unroll
    for(int j=0;j<4;j++)
      #pragma unroll
      for(int q=0;q<4;q++) acc[i][j][q]=0.f;

  // A loader: rows {arL, +32, +64, +96}, float4 at akL
  const int arL = (tid>>3);
  const int akL = (tid&7)*4;
  // B loader: row bnL (0..63), 8 bf16 (uint4) at bkL
  const int bnL = (tid>>2);
  const int bkL = (tid&3)*8;

  float4 pa[4]; uint4 pbh, pbl;
  const int totalChunks = gd.nterms*16;

  // ---- load chunk 0
  {
    const float* A = Aterm[0];
    #pragma unroll
    for(int it=0;it<4;it++){
      int r = arL + it*32;
      pa[it] = *(const float4*)(A + (size_t)(rowBase+r)*512 + akL);
      if(A2base){
        float4 u = *(const float4*)(A2base + (size_t)(rowBase+r)*512 + akL);
        pa[it].x*=u.x; pa[it].y*=u.y; pa[it].z*=u.z; pa[it].w*=u.w;
      }
    }
    pbh = *(const uint4*)(Whp[0] + (size_t)(colBase+bnL)*512 + bkL);
    pbl = *(const uint4*)(Wlp[0] + (size_t)(colBase+bnL)*512 + bkL);
  }
  // store chunk 0 -> buf 0
  {
    __nv_bfloat16* Ah = sm;
    __nv_bfloat16* Al = sm + PART_A;
    __nv_bfloat16* Bh = sm + 2*PART_A;
    __nv_bfloat16* Bl = sm + 2*PART_A + PART_B;
    #pragma unroll
    for(int it=0;it<4;it++){
      int r = arL + it*32;
      union { __nv_bfloat16 b[4]; uint2 u; } ph, pl;
      float xs[4]={pa[it].x,pa[it].y,pa[it].z,pa[it].w};
      #pragma unroll
      for(int j=0;j<4;j++){
        __nv_bfloat16 h = __float2bfloat16(xs[j]);
        ph.b[j]=h; pl.b[j]=__float2bfloat16(xs[j]-__bfloat162float(h));
      }
      *(uint2*)(Ah + r*SMS + akL) = ph.u;
      *(uint2*)(Al + r*SMS + akL) = pl.u;
    }
    *(uint2*)(Bh + bnL*SMS + bkL)     = make_uint2(pbh.x, pbh.y);
    *(uint2*)(Bh + bnL*SMS + bkL + 4) = make_uint2(pbh.z, pbh.w);
    *(uint2*)(Bl + bnL*SMS + bkL)     = make_uint2(pbl.x, pbl.y);
    *(uint2*)(Bl + bnL*SMS + bkL + 4) = make_uint2(pbl.z, pbl.w);
  }
  __syncthreads();

  const uint32_t smemBase = (uint32_t)__cvta_generic_to_shared(sm);
  int buf = 0;
  for(int ch=1; ch<=totalChunks; ch++){
    if(ch<totalChunks){
      int term = ch>>4; int k0 = (ch&15)*32;
      const float* A = Aterm[term];
      #pragma unroll
      for(int it=0;it<4;it++){
        int r = arL + it*32;
        pa[it] = *(const float4*)(A + (size_t)(rowBase+r)*512 + k0 + akL);
        if(A2base){
          float4 u = *(const float4*)(A2base + (size_t)(rowBase+r)*512 + k0 + akL);
          pa[it].x*=u.x; pa[it].y*=u.y; pa[it].z*=u.z; pa[it].w*=u.w;
        }
      }
      pbh = *(const uint4*)(Whp[term] + (size_t)(colBase+bnL)*512 + k0 + bkL);
      pbl = *(const uint4*)(Wlp[term] + (size_t)(colBase+bnL)*512 + k0 + bkL);
    }
    // compute current buf
    {
      uint32_t aH = smemBase + (uint32_t)(buf*STG)*2;
      uint32_t aL = aH + (uint32_t)PART_A*2;
      uint32_t bH = aH + (uint32_t)(2*PART_A)*2;
      uint32_t bL = bH + (uint32_t)PART_B*2;
      #pragma unroll
      for(int kk=0;kk<32;kk+=16){
        uint32_t bh0[4],bh1[4],bl0[4],bl1[4];
        #pragma unroll
        for(int pr=0; pr<2; pr++){
          int n = wc*32 + pr*16 + ((mi>>1)<<3) + wi;
          uint32_t off = (uint32_t)(n*SMS + kk + ((mi&1)<<3))*2;
          uint32_t r0,r1,r2,r3;
          ldsm4(r0,r1,r2,r3, bH + off);
          bh0[2*pr]=r0; bh1[2*pr]=r1; bh0[2*pr+1]=r2; bh1[2*pr+1]=r3;
          ldsm4(r0,r1,r2,r3, bL + off);
          bl0[2*pr]=r0; bl1[2*pr]=r1; bl0[2*pr+1]=r2; bl1[2*pr+1]=r3;
        }
        #pragma unroll
        for(int mb=0;mb<2;mb++){
          int row = wr*32 + mb*16 + ((mi&1)<<3) + wi;
          uint32_t off = (uint32_t)(row*SMS + kk + ((mi>>1)<<3))*2;
          uint32_t ah0,ah1,ah2,ah3, al0,al1,al2,al3;
          ldsm4(ah0,ah1,ah2,ah3, aH + off);
          ldsm4(al0,al1,al2,al3, aL + off);
          #pragma unroll
          for(int nb=0;nb<4;nb++){
            mma16816(acc[mb][nb], ah0,ah1,ah2,ah3, bh0[nb],bh1[nb]);
            mma16816(acc[mb][nb], ah0,ah1,ah2,ah3, bl0[nb],bl1[nb]);
            mma16816(acc[mb][nb], al0,al1,al2,al3, bh0[nb],bh1[nb]);
          }
        }
      }
    }
    if(ch<totalChunks){
      int nb2 = buf^1;
      __nv_bfloat16* Ah = sm + nb2*STG;
      __nv_bfloat16* Al = Ah + PART_A;
      __nv_bfloat16* Bh = Ah + 2*PART_A;
      __nv_bfloat16* Bl = Ah + 2*PART_A + PART_B;
      #pragma unroll
      for(int it=0;it<4;it++){
        int r = arL + it*32;
        union { __nv_bfloat16 b[4]; uint2 u; } ph, pl;
        float xs[4]={pa[it].x,pa[it].y,pa[it].z,pa[it].w};
        #pragma unroll
        for(int j=0;j<4;j++){
          __nv_bfloat16 h = __float2bfloat16(xs[j]);
          ph.b[j]=h; pl.b[j]=__float2bfloat16(xs[j]-__bfloat162float(h));
        }
        *(uint2*)(Ah + r*SMS + akL) = ph.u;
        *(uint2*)(Al + r*SMS + akL) = pl.u;
      }
      *(uint2*)(Bh + bnL*SMS + bkL)     = make_uint2(pbh.x, pbh.y);
      *(uint2*)(Bh + bnL*SMS + bkL + 4) = make_uint2(pbh.z, pbh.w);
      *(uint2*)(Bl + bnL*SMS + bkL)     = make_uint2(pbl.x, pbl.y);
      *(uint2*)(Bl + bnL*SMS + bkL + 4) = make_uint2(pbl.z, pbl.w);
      __syncthreads();
      buf = nb2;
    }
  }

  // ---- epilogue
  const float* bias = nullptr;
  if(gd.bKind==0)      bias = edge_b + (size_t)gd.bIdx*512;
  else if(gd.bKind==1) bias = node_b + (size_t)gd.bIdx*512;
  const float* res = (gd.resBuf>=0)? bufPtrC(gd.resBuf,inpute,inputo) : nullptr;
  float* dst = bufPtrM(gd.dstBuf);
  #pragma unroll
  for(int mb=0;mb<2;mb++){
    #pragma unroll
    for(int nb=0;nb<4;nb++){
      int row0 = rowBase + wr*32 + mb*16 + g8;
      int col0 = colBase + wc*32 + nb*8 + tg*2;
      #pragma unroll
      for(int half=0; half<2; half++){
        int row = row0 + half*8;
        float z0 = acc[mb][nb][half*2+0] + (bias? bias[col0]:0.f);
        float z1 = acc[mb][nb][half*2+1] + (bias? bias[col0+1]:0.f);
        if(gd.actCode==1){ z0=fmaxf(z0,0.f); z1=fmaxf(z1,0.f); }
        else if(gd.actCode==2){ z0=geluf(z0); z1=geluf(z1); }
        if(res){
          float2 rv = *(const float2*)(res + (size_t)row*512 + col0);
          z0 += rv.x; z1 += rv.y;
        }
        float2 ov; ov.x = gd.scale*z0; ov.y = gd.scale*z1;
        *(float2*)(dst + (size_t)row*512 + col0) = ov;
      }
    }
  }
}

// ---------------- tensor-core flash attention (unchanged from best passing version) ----------------
#define ASROW 72
#define AQ_H 0
#define AQ_L 9216
#define AK_H 18432
#define AK_L 23040
#define AV_H 27648
#define AV_L 32256
#define ATTN_SMEM_ELEMS 36864

__device__ __forceinline__ void ldsm4t(uint32_t& r0,uint32_t& r1,uint32_t& r2,uint32_t& r3, uint32_t saddr){
  asm volatile("ldmatrix.sync.aligned.m8n8.x4.trans.shared.b16 {%0,%1,%2,%3}, [%4];"
    : "=r"(r0),"=r"(r1),"=r"(r2),"=r"(r3) : "r"(saddr));
}
__device__ __forceinline__ void split2(float a, float b, uint32_t& hi, uint32_t& lo){
  __nv_bfloat16 ha=__float2bfloat16(a), hb=__float2bfloat16(b);
  __nv_bfloat162 hh; hh.x=ha; hh.y=hb; hi = *(uint32_t*)&hh;
  __nv_bfloat162 ll; ll.x=__float2bfloat16(a-__bfloat162float(ha));
  ll.y=__float2bfloat16(b-__bfloat162float(hb)); lo = *(uint32_t*)&ll;
}

__global__ void __launch_bounds__(256,1) attn_kernel(int c){
  if(g_node_act[c]!=0) return;
  extern __shared__ __nv_bfloat16 asm_[];
  const int tid = threadIdx.x;
  const int lane = tid & 31;
  const int wid = tid >> 5;
  const int mi = lane>>3, wi = lane&7;
  const int g8 = lane>>2, tg = lane&3;
  const int bh = blockIdx.y; const int b = bh>>3, h = bh&7;
  const int q0 = blockIdx.x*128;
  const float* Q = g_tt[0]; const float* K = g_tt[1]; const float* V = g_tt[2];
  const uint32_t smemBase = (uint32_t)__cvta_generic_to_shared(asm_);

  {
    int row = tid>>1;
    int col0 = (tid&1)*32;
    const float* src = Q + ((size_t)(b*1024+q0+row))*DIM + h*64 + col0;
    #pragma unroll
    for(int j=0;j<8;j++){
      float4 v = *(const float4*)(src + j*4);
      uint32_t h0,l0,h1,l1;
      split2(v.x,v.y,h0,l0); split2(v.z,v.w,h1,l1);
      int o = row*ASROW + col0 + j*4;
      *(uint32_t*)(asm_+AQ_H+o)   = h0; *(uint32_t*)(asm_+AQ_H+o+2) = h1;
      *(uint32_t*)(asm_+AQ_L+o)   = l0; *(uint32_t*)(asm_+AQ_L+o+2) = l1;
    }
  }
  __syncthreads();

  uint32_t qh[4][4], ql[4][4];
  {
    int row = wid*16 + ((mi&1)<<3) + wi;
    #pragma unroll
    for(int ks=0;ks<4;ks++){
      uint32_t off = (uint32_t)(row*ASROW + ks*16 + ((mi>>1)<<3))*2;
      ldsm4(qh[ks][0],qh[ks][1],qh[ks][2],qh[ks][3], smemBase + AQ_H*2 + off);
      ldsm4(ql[ks][0],ql[ks][1],ql[ks][2],ql[ks][3], smemBase + AQ_L*2 + off);
    }
  }

  float o_acc[8][4];
  #pragma unroll
  for(int nb=0;nb<8;nb++)
    #pragma unroll
    for(int q=0;q<4;q++) o_acc[nb][q]=0.f;
  float m_st[2] = {-1e30f,-1e30f};
  float l_st[2] = {0.f,0.f};

  for(int chunk=0; chunk<16; chunk++){
    __syncthreads();
    {
      int key = tid>>2;
      int col0 = (tid&3)*16;
      size_t base = ((size_t)(b*1024 + chunk*64 + key))*DIM + h*64 + col0;
      #pragma unroll
      for(int j=0;j<4;j++){
        float4 kv = *(const float4*)(K + base + j*4);
        float4 vv = *(const float4*)(V + base + j*4);
        uint32_t h0,l0,h1,l1;
        int o = key*ASROW + col0 + j*4;
        split2(kv.x,kv.y,h0,l0); split2(kv.z,kv.w,h1,l1);
        *(uint32_t*)(asm_+AK_H+o) = h0; *(uint32_t*)(asm_+AK_H+o+2) = h1;
        *(uint32_t*)(asm_+AK_L+o) = l0; *(uint32_t*)(asm_+AK_L+o+2) = l1;
        split2(vv.x,vv.y,h0,l0); split2(vv.z,vv.w,h1,l1);
        *(uint32_t*)(asm_+AV_H+o) = h0; *(uint32_t*)(asm_+AV_H+o+2) = h1;
        *(uint32_t*)(asm_+AV_L+o) = l0; *(uint32_t*)(asm_+AV_L+o+2) = l1;
      }
    }
    __syncthreads();

    float s[8][4];
    #pragma unroll
    for(int nb=0;nb<8;nb++)
      #pragma unroll
      for(int q=0;q<4;q++) s[nb][q]=0.f;
    #pragma unroll
    for(int ks=0;ks<4;ks++){
      uint32_t kb0[8], kb1[8], klo0[8], klo1[8];
      #pragma unroll
      for(int pr=0;pr<4;pr++){
        int n = pr*16 + ((mi>>1)<<3) + wi;
        uint32_t off = (uint32_t)(n*ASROW + ks*16 + ((mi&1)<<3))*2;
        uint32_t r0,r1,r2,r3;
        ldsm4(r0,r1,r2,r3, smemBase + AK_H*2 + off);
        kb0[2*pr]=r0; kb1[2*pr]=r1; kb0[2*pr+1]=r2; kb1[2*pr+1]=r3;
        ldsm4(r0,r1,r2,r3, smemBase + AK_L*2 + off);
        klo0[2*pr]=r0; klo1[2*pr]=r1; klo0[2*pr+1]=r2; klo1[2*pr+1]=r3;
      }
      #pragma unroll
      for(int nb=0;nb<8;nb++){
        mma16816(s[nb], qh[ks][0],qh[ks][1],qh[ks][2],qh[ks][3], kb0[nb],kb1[nb]);
        mma16816(s[nb], qh[ks][0],qh[ks][1],qh[ks][2],qh[ks][3], klo0[nb],klo1[nb]);
        mma16816(s[nb], ql[ks][0],ql[ks][1],ql[ks][2],ql[ks][3], kb0[nb],kb1[nb]);
      }
    }

    float p[8][4];
    #pragma unroll
    for(int hr=0;hr<2;hr++){
      float mloc = -1e30f;
      #pragma unroll
      for(int nb=0;nb<8;nb++){
        float a = s[nb][hr*2+0]*0.125f, bb = s[nb][hr*2+1]*0.125f;
        s[nb][hr*2+0]=a; s[nb][hr*2+1]=bb;
        mloc = fmaxf(mloc, fmaxf(a,bb));
      }
      mloc = fmaxf(mloc, __shfl_xor_sync(0xffffffffu, mloc, 1));
      mloc = fmaxf(mloc, __shfl_xor_sync(0xffffffffu, mloc, 2));
      float m_new = fmaxf(m_st[hr], mloc);
      float corr = __expf(m_st[hr]-m_new);
      float lloc = 0.f;
      #pragma unroll
      for(int nb=0;nb<8;nb++){
        float p0 = __expf(s[nb][hr*2+0]-m_new);
        float p1 = __expf(s[nb][hr*2+1]-m_new);
        p[nb][hr*2+0]=p0; p[nb][hr*2+1]=p1;
        lloc += p0+p1;
      }
      lloc += __shfl_xor_sync(0xffffffffu, lloc, 1);
      lloc += __shfl_xor_sync(0xffffffffu, lloc, 2);
      l_st[hr] = l_st[hr]*corr + lloc;
      m_st[hr] = m_new;
      #pragma unroll
      for(int nb=0;nb<8;nb++){ o_acc[nb][hr*2+0]*=corr; o_acc[nb][hr*2+1]*=corr; }
    }

    #pragma unroll
    for(int ks=0;ks<4;ks++){
      uint32_t pa0,pa1,pa2,pa3, pl0,pl1,pl2,pl3;
      split2(p[2*ks][0],   p[2*ks][1],   pa0, pl0);
      split2(p[2*ks][2],   p[2*ks][3],   pa1, pl1);
      split2(p[2*ks+1][0], p[2*ks+1][1], pa2, pl2);
      split2(p[2*ks+1][2], p[2*ks+1][3], pa3, pl3);
      #pragma unroll
      for(int pr=0;pr<4;pr++){
        int key = ks*16 + ((mi&1)<<3) + wi;
        int d0  = pr*16 + ((mi>>1)<<3);
        uint32_t off = (uint32_t)(key*ASROW + d0)*2;
        uint32_t vh0,vh1,vh2,vh3, vl0,vl1,vl2,vl3;
        ldsm4t(vh0,vh1,vh2,vh3, smemBase + AV_H*2 + off);
        ldsm4t(vl0,vl1,vl2,vl3, smemBase + AV_L*2 + off);
        mma16816(o_acc[2*pr],   pa0,pa1,pa2,pa3, vh0,vh1);
        mma16816(o_acc[2*pr],   pa0,pa1,pa2,pa3, vl0,vl1);
        mma16816(o_acc[2*pr],   pl0,pl1,pl2,pl3, vh0,vh1);
        mma16816(o_acc[2*pr+1], pa0,pa1,pa2,pa3, vh2,vh3);
        mma16816(o_acc[2*pr+1], pa0,pa1,pa2,pa3, vl2,vl3);
        mma16816(o_acc[2*pr+1], pl0,pl1,pl2,pl3, vh2,vh3);
      }
    }
  }

  #pragma unroll
  for(int hr=0;hr<2;hr++){
    float inv = 1.f/l_st[hr];
    int row = q0 + wid*16 + hr*8 + g8;
    #pragma unroll
    for(int nb=0;nb<8;nb++){
      int col = h*64 + nb*8 + tg*2;
      float2 ov; ov.x = o_acc[nb][hr*2+0]*inv; ov.y = o_acc[nb][hr*2+1]*inv;
      *(float2*)(g_attn + ((size_t)(b*1024+row))*DIM + col) = ov;
    }
  }
}

// ---------------- elementwise node ops (warp-per-row) ----------------
__global__ void post_elt(int c, const float* __restrict__ node_g, const float* __restrict__ node_beta){
  int act = g_node_act[c];
  if(act==0||act==1||act==3) return;
  float aw = g_node_aw[c];
  int wid = threadIdx.x>>5, lane = threadIdx.x&31;
  int row = blockIdx.x*8 + wid;
  size_t off=(size_t)row*DIM;
  const float* q=g_qkv[0]+off; const float* k=g_qkv[1]+off; const float* v=g_qkv[2]+off;
  float* o = g_outbuf[c]+off;
  if(act==4||act==5||act==6){
    #pragma unroll
    for(int j=0;j<4;j++){
      int col = lane*4 + j*128;
      float4 qv = *(const float4*)(q+col);
      float4 ov;
      if(act==4){
        float4 kv = *(const float4*)(k+col);
        float4 vv = *(const float4*)(v+col);
        ov.x=aw*(qv.x*sigmoidf(kv.x)+vv.x); ov.y=aw*(qv.y*sigmoidf(kv.y)+vv.y);
        ov.z=aw*(qv.z*sigmoidf(kv.z)+vv.z); ov.w=aw*(qv.w*sigmoidf(kv.w)+vv.w);
      } else if(act==5){
        float4 tv = *(const float4*)(g_tt[0]+off+col);
        ov.x=aw*(qv.x+tv.x); ov.y=aw*(qv.y+tv.y); ov.z=aw*(qv.z+tv.z); ov.w=aw*(qv.w+tv.w);
      } else {
        float4 kv = *(const float4*)(k+col);
        ov.x=aw*(qv.x+kv.x); ov.y=aw*(qv.y+kv.y); ov.z=aw*(qv.z+kv.z); ov.w=aw*(qv.w+kv.w);
      }
      *(float4*)(o+col)=ov;
    }
    return;
  }
  float4 x[4];
  #pragma unroll
  for(int j=0;j<4;j++){
    int col = lane*4 + j*128;
    float4 qv = *(const float4*)(q+col);
    if(act==2){
      float4 kv = *(const float4*)(k+col);
      float4 vv = *(const float4*)(v+col);
      qv.x+=kv.x+vv.x; qv.y+=kv.y+vv.y; qv.z+=kv.z+vv.z; qv.w+=kv.w+vv.w;
    }
    x[j]=qv;
  }
  float s=0.f;
  #pragma unroll
  for(int j=0;j<4;j++) s += x[j].x+x[j].y+x[j].z+x[j].w;
  float mean = warpReduceSum(s)*(1.f/512.f);
  float s2=0.f;
  #pragma unroll
  for(int j=0;j<4;j++){
    float a=x[j].x-mean,b=x[j].y-mean,cc=x[j].z-mean,dd=x[j].w-mean;
    s2 += a*a+b*b+cc*cc+dd*dd;
  }
  float rstd = rsqrtf(warpReduceSum(s2)*(1.f/512.f)+1e-6f);
  const float* g  = node_g    + (size_t)c*DIM;
  const float* be = node_beta + (size_t)c*DIM;
  #pragma unroll
  for(int j=0;j<4;j++){
    int col = lane*4 + j*128;
    float4 gv = *(const float4*)(g+col);
    float4 bv = *(const float4*)(be+col);
    float4 ov;
    ov.x=aw*((x[j].x-mean)*rstd*gv.x+bv.x); ov.y=aw*((x[j].y-mean)*rstd*gv.y+bv.y);
    ov.z=aw*((x[j].z-mean)*rstd*gv.z+bv.z); ov.w=aw*((x[j].w-mean)*rstd*gv.w+bv.w);
    *(float4*)(o+col)=ov;
  }
}

// ---------------- final: sum remaining nodes + LN (warp-per-row) ----------------
__global__ void final_kernel(const float* __restrict__ og, const float* __restrict__ obe, float* __restrict__ out){
  int wid = threadIdx.x>>5, lane = threadIdx.x&31;
  int row = blockIdx.x*8 + wid;
  int mask = g_rem_mask;
  size_t off=(size_t)row*DIM;
  float4 x[4];
  #pragma unroll
  for(int j=0;j<4;j++){ x[j].x=0;x[j].y=0;x[j].z=0;x[j].w=0; }
  #pragma unroll
  for(int i=0;i<8;i++) if((mask>>i)&1){
    #pragma unroll
    for(int j=0;j<4;j++){
      float4 v = *(const float4*)(g_outbuf[i]+off+lane*4+j*128);
      x[j].x+=v.x; x[j].y+=v.y; x[j].z+=v.z; x[j].w+=v.w;
    }
  }
  float s=0.f;
  #pragma unroll
  for(int j=0;j<4;j++) s += x[j].x+x[j].y+x[j].z+x[j].w;
  float mean = warpReduceSum(s)*(1.f/512.f);
  float s2=0.f;
  #pragma unroll
  for(int j=0;j<4;j++){
    float a=x[j].x-mean,b=x[j].y-mean,cc=x[j].z-mean,dd=x[j].w-mean;
    s2 += a*a+b*b+cc*cc+dd*dd;
  }
  float rstd = rsqrtf(warpReduceSum(s2)*(1.f/512.f)+1e-6f);
  #pragma unroll
  for(int j=0;j<4;j++){
    int col = lane*4 + j*128;
    float4 gv = *(const float4*)(og+col);
    float4 bv = *(const float4*)(obe+col);
    float4 ov;
    ov.x=(x[j].x-mean)*rstd*gv.x+bv.x; ov.y=(x[j].y-mean)*rstd*gv.y+bv.y;
    ov.z=(x[j].z-mean)*rstd*gv.z+bv.z; ov.w=(x[j].w-mean)*rstd*gv.w+bv.w;
    *(float4*)(out+off+col)=ov;
  }
}

extern "C" void kernel_launch(void* const* d_in, const int* in_sizes, int n_in,
                              void* d_out, int out_size) {
  (void)in_sizes; (void)n_in; (void)out_size;
  const float* inpute    = (const float*)d_in[0];
  const float* inputo    = (const float*)d_in[1];
  const float* node_p    = (const float*)d_in[2];
  const float* edge_p    = (const float*)d_in[3];
  const float* edge_W    = (const float*)d_in[4];
  const float* edge_b    = (const float*)d_in[5];
  const float* edge_g    = (const float*)d_in[6];
  const float* edge_beta = (const float*)d_in[7];
  const float* node_W    = (const float*)d_in[8];
  const float* node_b    = (const float*)d_in[9];
  const float* node_g    = (const float*)d_in[10];
  const float* node_beta = (const float*)d_in[11];
  const float* out_g     = (const float*)d_in[12];
  const float* out_beta  = (const float*)d_in[13];
  float* out = (float*)d_out;

  const int gemmSmem = 2*STG*(int)sizeof(__nv_bfloat16); // 61440 bytes
  cudaFuncSetAttribute(gemm_kernel, cudaFuncAttributeMaxDynamicSharedMemorySize, gemmSmem);
  const int attnSmem = ATTN_SMEM_ELEMS*(int)sizeof(__nv_bfloat16); // 73728 bytes
  cudaFuncSetAttribute(attn_kernel, cudaFuncAttributeMaxDynamicSharedMemorySize, attnSmem);

  route_kernel<<<1,1>>>(node_p, edge_p);
  convw_kernel<<<dim3(16,16,66),256>>>(edge_W, node_W);
  for(int c=0;c<8;c++){
    prep_kernel<<<dim3(512,1,3),256>>>(c, inpute, inputo, edge_g, edge_beta);
    gemm_kernel<<<dim3(8,32,3),256,gemmSmem>>>(c,0,inpute,inputo,edge_b,node_b);
    lnq_kernel<<<512,256>>>(c, node_g, node_beta);
    gemm_kernel<<<dim3(8,32,3),256,gemmSmem>>>(c,3,inpute,inputo,edge_b,node_b);
    attn_kernel<<<dim3(8,32),256,attnSmem>>>(c);
    gemm_kernel<<<dim3(8,32,1),256,gemmSmem>>>(c,6,inpute,inputo,edge_b,node_b);
    post_elt<<<512,256>>>(c, node_g, node_beta);
  }
  final_kernel<<<512,256>>>(out_g, out_beta, out);
}

// round 16
// speedup vs baseline: 1.5927x; 1.3772x over previous
#include <cuda_runtime.h>
#include <cuda_bf16.h>
#include <cuda_fp16.h>
#include <math.h>
#include <stdint.h>

#define NROWS 4096
#define DIM 512

// ---------------- descriptors ----------------
struct ERole { int enabled; int src; int e; int op; float w; };
struct GemmDesc {
  int enabled, nterms, mul;
  int srcA[3];
  int wKind[3], wIdx[3];
  int bKind, bIdx;
  int actCode;          // 0 none, 1 relu, 2 gelu
  int resBuf, dstBuf;
  float scale;
};

__device__ ERole    g_erole[8][3];
__device__ GemmDesc g_gd[8][7];
__device__ int      g_node_act[8];
__device__ float    g_node_aw[8];
__device__ int      g_rem_mask;

// ---------------- big scratch buffers ----------------
__device__ float g_outbuf[8][NROWS*DIM];
__device__ float g_qkv[3][NROWS*DIM];
__device__ float g_prep[3][NROWS*DIM];
__device__ float g_tt[3][NROWS*DIM];
__device__ float g_lnq[NROWS*DIM];
__device__ float g_attn[NROWS*DIM];

// transposed fp16 weights: [w][n*512+k]. w: 0..33 edge, 34..65 node
__device__ __half g_Wt[66u*262144u];

// buffer id map: 0 inpute, 1 inputo, 2..9 outbuf, 10..12 qkv, 13..15 prep, 16..18 tt, 19 lnq, 20 attn
__device__ __forceinline__ const float* bufPtrC(int id, const float* inpute, const float* inputo){
  if(id==0) return inpute;
  if(id==1) return inputo;
  if(id<10) return g_outbuf[id-2];
  if(id<13) return g_qkv[id-10];
  if(id<16) return g_prep[id-13];
  if(id<19) return g_tt[id-16];
  if(id==19) return g_lnq;
  return g_attn;
}
__device__ __forceinline__ float* bufPtrM(int id){
  if(id<10) return g_outbuf[id-2];
  if(id<13) return g_qkv[id-10];
  if(id<16) return g_prep[id-13];
  if(id<19) return g_tt[id-16];
  if(id==19) return g_lnq;
  return g_attn;
}

__device__ __forceinline__ float geluf(float x){
  float inner = 0.7978845608028654f*(x + 0.044715f*x*x*x);
  return 0.5f*x*(1.f+tanhf(inner));
}
__device__ __forceinline__ float sigmoidf(float x){ return 1.f/(1.f+expf(-x)); }

__device__ __forceinline__ float warpReduceSum(float v){
  #pragma unroll
  for(int o=16;o;o>>=1) v += __shfl_xor_sync(0xffffffffu, v, o);
  return v;
}

// ---------------- routing ----------------
__device__ void selrange(const float* p, int lo, int hi, int& sel, float& w){
  int bi=lo; float bv=p[lo];
  for(int i=lo+1;i<hi;i++) if(p[i]>bv){bv=p[i];bi=i;}
  float s=0.f;
  for(int i=lo;i<hi;i++) s += expf(p[i]-bv);
  sel=bi; w=1.f/s;
}

__device__ void fillRole(int c,int role,int sel,float w,int lind,int snode,int& processed,int computeEnabled){
  int se = sel/5, op = sel%5;
  int inn = (se==0)? -2 : snode+se;
  if(inn>=0) processed |= (1<<inn);
  int src = (inn==-2)?0 : ((inn==-1)?1 : (2+inn));
  ERole er; er.enabled=computeEnabled; er.src=src; er.e=lind+se; er.op=op; er.w=w;
  g_erole[c][role]=er;
}

__device__ void setGemm(int c,int slot,int src0,int wKind0,int wIdx0,int bKind,int bIdx,
                        int actCode,int resBuf,int dstBuf,float scale){
  GemmDesc gd;
  gd.enabled=1; gd.nterms=1; gd.mul=0;
  gd.srcA[0]=src0; gd.srcA[1]=0; gd.srcA[2]=0;
  gd.wKind[0]=wKind0; gd.wIdx[0]=wIdx0;
  gd.wKind[1]=0; gd.wIdx[1]=0; gd.wKind[2]=0; gd.wIdx[2]=0;
  gd.bKind=bKind; gd.bIdx=bIdx;
  gd.actCode=actCode; gd.resBuf=resBuf; gd.dstBuf=dstBuf; gd.scale=scale;
  g_gd[c][slot]=gd;
}

__global__ void route_kernel(const float* __restrict__ node_p, const float* __restrict__ edge_p){
  if(threadIdx.x!=0 || blockIdx.x!=0) return;
  int processed = 0;
  int lind = 0;
  for(int c=0;c<8;c++){
    for(int s=0;s<7;s++) g_gd[c][s].enabled=0;
    for(int r=0;r<3;r++) g_erole[c][r].enabled=0;

    int nsrc = (c+2<5)? c+2 : 5;
    int snode = c - nsrc;
    int L = nsrc*5;
    const float* ep0 = edge_p + lind*5;
    const float* ep1 = edge_p + 170 + lind*5;
    const float* ep2 = edge_p + 340 + lind*5;
    const float* np  = node_p + c*8;

    int act=0; { float b=np[0]; for(int i=1;i<8;i++) if(np[i]>b){b=np[i];act=i;} }
    float aw;
    { float m=np[0]; for(int i=1;i<8;i++) m=fmaxf(m,np[i]);
      float s=0.f; for(int i=0;i<8;i++) s+=expf(np[i]-m);
      aw = expf(np[act]-m)/s; }
    g_node_act[c]=act; g_node_aw[c]=aw;

    int qsel; float qw;
    selrange(ep0, 5, L, qsel, qw);
    fillRole(c,0,qsel,qw,lind,snode,processed,1);

    int ksel = -1;
    if(act<7){
      int lo = (act>0)?5:0;
      float kw;
      selrange(ep1, lo, L, ksel, kw);
      fillRole(c,1,ksel,kw,lind,snode,processed,1);
    }
    if(act<5){
      int vsel; float vw;
      if(act==0 && (ksel/5)==0){
        selrange(ep2, 0, 5, vsel, vw);
      } else {
        int lo = (act>0)?5:0;
        selrange(ep2, lo, L, vsel, vw);
      }
      fillRole(c,2,vsel,vw,lind,snode,processed,(act!=1)?1:0);
    }

    for(int r2=0;r2<3;r2++){
      ERole er = g_erole[c][r2];
      if(er.enabled && er.op!=4){
        int ac = (er.op==0)?1:((er.op==1)?2:0);
        setGemm(c, r2, 13+r2, 0, er.e, 0, er.e, ac, -1, 10+r2, er.w);
      }
    }

    int cw = c*4;
    if(act==0){
      setGemm(c,3,19,1,cw+0,1,cw+0,0,-1,16,1.f);
      setGemm(c,4,11,1,cw+1,1,cw+1,0,-1,17,1.f);
      setGemm(c,5,12,1,cw+2,1,cw+2,0,-1,18,1.f);
      setGemm(c,6,20,1,cw+3,1,cw+3,0,10,2+c,aw);
    } else if(act==1){
      setGemm(c,3,10,1,cw+0,1,cw+0,2,-1,16,1.f);
      setGemm(c,4,11,1,cw+1,1,cw+1,0,-1,17,1.f);
      setGemm(c,6,16,1,cw+3,1,cw+3,0,10,2+c,aw);
      g_gd[c][6].mul=1; g_gd[c][6].srcA[1]=17;
    } else if(act==3){
      setGemm(c,3,10,1,cw+0,-1,0,1,-1,16,1.f);
      g_gd[c][3].nterms=3;
      g_gd[c][3].srcA[1]=11; g_gd[c][3].srcA[2]=12;
      g_gd[c][3].wKind[1]=1; g_gd[c][3].wIdx[1]=cw+1;
      g_gd[c][3].wKind[2]=1; g_gd[c][3].wIdx[2]=cw+2;
      setGemm(c,6,16,1,cw+3,1,cw+3,0,10,2+c,aw);
    } else if(act==5){
      setGemm(c,3,11,1,cw+1,1,cw+1,2,-1,16,1.f);
    }

    lind += nsrc;
  }
  g_rem_mask = (~processed) & 0xFF;
}

// ---------------- weight conversion: fp32 [k][n] -> fp16 transposed [n][k] ----------------
__global__ void convw_kernel(const float* __restrict__ eW, const float* __restrict__ nW){
  __shared__ float tile[32][33];
  int w = blockIdx.z;
  const float* src = (w<34) ? eW + (size_t)w*262144 : nW + (size_t)(w-34)*262144;
  int k0 = blockIdx.x*32, n0 = blockIdx.y*32;
  int tr = threadIdx.x>>3;
  int tc = (threadIdx.x&7)*4;
  float4 v = *(const float4*)(src + (size_t)(k0+tr)*512 + n0+tc);
  tile[tr][tc+0]=v.x; tile[tr][tc+1]=v.y; tile[tr][tc+2]=v.z; tile[tr][tc+3]=v.w;
  __syncthreads();
  int nr = threadIdx.x>>3;
  int kc = (threadIdx.x&7)*4;
  union { __half b[4]; uint2 u; } ph;
  #pragma unroll
  for(int j=0;j<4;j++) ph.b[j] = __float2half_rn(tile[kc+j][nr]);
  size_t off = (size_t)w*262144 + (size_t)(n0+nr)*512 + k0+kc;
  *(uint2*)(g_Wt + off) = ph.u;
}

// ---------------- edge prep (warp-per-row) ----------------
__global__ void prep_kernel(int c, const float* __restrict__ inpute, const float* __restrict__ inputo,
                            const float* __restrict__ edge_g, const float* __restrict__ edge_beta){
  int role = blockIdx.z;
  ERole er = g_erole[c][role];
  if(!er.enabled) return;
  int wid = threadIdx.x>>5, lane = threadIdx.x&31;
  int row = blockIdx.x*8 + wid;
  const float* x = bufPtrC(er.src, inpute, inputo) + (size_t)row*DIM;
  float4 v[4];
  #pragma unroll
  for(int j=0;j<4;j++) v[j] = *(const float4*)(x + lane*4 + j*128);
  if(er.op==4){
    float* d = g_qkv[role] + (size_t)row*DIM;
    #pragma unroll
    for(int j=0;j<4;j++){
      float4 o; o.x=er.w*v[j].x; o.y=er.w*v[j].y; o.z=er.w*v[j].z; o.w=er.w*v[j].w;
      *(float4*)(d + lane*4 + j*128) = o;
    }
    return;
  }
  if(er.op==3){
    float* d = g_prep[role] + (size_t)row*DIM;
    #pragma unroll
    for(int j=0;j<4;j++) *(float4*)(d + lane*4 + j*128) = v[j];
    return;
  }
  float s=0.f;
  #pragma unroll
  for(int j=0;j<4;j++) s += v[j].x+v[j].y+v[j].z+v[j].w;
  float mean = warpReduceSum(s)*(1.f/512.f);
  float s2=0.f;
  #pragma unroll
  for(int j=0;j<4;j++){
    float a=v[j].x-mean,b=v[j].y-mean,cc=v[j].z-mean,dd=v[j].w-mean;
    s2 += a*a+b*b+cc*cc+dd*dd;
  }
  float rstd = rsqrtf(warpReduceSum(s2)*(1.f/512.f)+1e-6f);
  const float* g  = edge_g    + (size_t)er.e*DIM;
  const float* be = edge_beta + (size_t)er.e*DIM;
  float* d = g_prep[role] + (size_t)row*DIM;
  #pragma unroll
  for(int j=0;j<4;j++){
    int col = lane*4 + j*128;
    float4 gv = *(const float4*)(g+col);
    float4 bv = *(const float4*)(be+col);
    float4 o;
    o.x=(v[j].x-mean)*rstd*gv.x+bv.x; o.y=(v[j].y-mean)*rstd*gv.y+bv.y;
    o.z=(v[j].z-mean)*rstd*gv.z+bv.z; o.w=(v[j].w-mean)*rstd*gv.w+bv.w;
    *(float4*)(d+col)=o;
  }
}

// ---------------- LN(q) for MHA (warp-per-row) ----------------
__global__ void lnq_kernel(int c, const float* __restrict__ node_g, const float* __restrict__ node_beta){
  if(g_node_act[c]!=0) return;
  int wid = threadIdx.x>>5, lane = threadIdx.x&31;
  int row = blockIdx.x*8 + wid;
  const float* x = g_qkv[0] + (size_t)row*DIM;
  float4 v[4];
  #pragma unroll
  for(int j=0;j<4;j++) v[j] = *(const float4*)(x + lane*4 + j*128);
  float s=0.f;
  #pragma unroll
  for(int j=0;j<4;j++) s += v[j].x+v[j].y+v[j].z+v[j].w;
  float mean = warpReduceSum(s)*(1.f/512.f);
  float s2=0.f;
  #pragma unroll
  for(int j=0;j<4;j++){
    float a=v[j].x-mean,b=v[j].y-mean,cc=v[j].z-mean,dd=v[j].w-mean;
    s2 += a*a+b*b+cc*cc+dd*dd;
  }
  float rstd = rsqrtf(warpReduceSum(s2)*(1.f/512.f)+1e-6f);
  const float* g  = node_g    + (size_t)c*DIM;
  const float* be = node_beta + (size_t)c*DIM;
  float* d = g_lnq + (size_t)row*DIM;
  #pragma unroll
  for(int j=0;j<4;j++){
    int col = lane*4 + j*128;
    float4 gv = *(const float4*)(g+col);
    float4 bv = *(const float4*)(be+col);
    float4 o;
    o.x=(v[j].x-mean)*rstd*gv.x+bv.x; o.y=(v[j].y-mean)*rstd*gv.y+bv.y;
    o.z=(v[j].z-mean)*rstd*gv.z+bv.z; o.w=(v[j].w-mean)*rstd*gv.w+bv.w;
    *(float4*)(d+col)=o;
  }
}

// ---------------- tensor-core GEMM: fp16 single-product, 128x64 tile, 2 CTA/SM ----------------
#define SMS 40
#define PART_A (128*SMS)    // 5120 elems
#define PART_B (64*SMS)     // 2560 elems
#define STG (PART_A + PART_B)  // 7680 elems per stage

__device__ __forceinline__ void ldsm4(uint32_t& r0,uint32_t& r1,uint32_t& r2,uint32_t& r3, uint32_t saddr){
  asm volatile("ldmatrix.sync.aligned.m8n8.x4.shared.b16 {%0,%1,%2,%3}, [%4];"
    : "=r"(r0),"=r"(r1),"=r"(r2),"=r"(r3) : "r"(saddr));
}
__device__ __forceinline__ void mma16816h(float* c, uint32_t a0,uint32_t a1,uint32_t a2,uint32_t a3,
                                          uint32_t b0, uint32_t b1){
  asm volatile("mma.sync.aligned.m16n8k16.row.col.f32.f16.f16.f32 "
    "{%0,%1,%2,%3}, {%4,%5,%6,%7}, {%8,%9}, {%0,%1,%2,%3};"
    : "+f"(c[0]),"+f"(c[1]),"+f"(c[2]),"+f"(c[3])
    : "r"(a0),"r"(a1),"r"(a2),"r"(a3),"r"(b0),"r"(b1));
}
__device__ __forceinline__ void mma16816(float* c, uint32_t a0,uint32_t a1,uint32_t a2,uint32_t a3,
                                         uint32_t b0, uint32_t b1){
  asm volatile("mma.sync.aligned.m16n8k16.row.col.f32.bf16.bf16.f32 "
    "{%0,%1,%2,%3}, {%4,%5,%6,%7}, {%8,%9}, {%0,%1,%2,%3};"
    : "+f"(c[0]),"+f"(c[1]),"+f"(c[2]),"+f"(c[3])
    : "r"(a0),"r"(a1),"r"(a2),"r"(a3),"r"(b0),"r"(b1));
}

__global__ void __launch_bounds__(256,2) gemm_kernel(int c,int slotBase,
  const float* __restrict__ inpute,const float* __restrict__ inputo,
  const float* __restrict__ edge_b,const float* __restrict__ node_b)
{
  GemmDesc gd = g_gd[c][slotBase + blockIdx.z];
  if(!gd.enabled) return;
  extern __shared__ __half sm[];
  const int rowBase = blockIdx.y*128;
  const int colBase = blockIdx.x*64;
  const int tid = threadIdx.x;
  const int lane = tid & 31;
  const int wid = tid >> 5;
  const int wr = wid >> 1;
  const int wc = wid & 1;
  const int mi = lane>>3, wi = lane&7;
  const int g8 = lane >> 2, tg = lane & 3;

  const float* Aterm[3];
  const __half* Wp[3];
  for(int t=0;t<gd.nterms;t++){
    Aterm[t] = bufPtrC(gd.srcA[t],inpute,inputo);
    int wg = gd.wKind[t] ? (34+gd.wIdx[t]) : gd.wIdx[t];
    Wp[t] = g_Wt + (size_t)wg*262144;
  }
  const float* A2base = gd.mul ? bufPtrC(gd.srcA[1],inpute,inputo) : nullptr;

  float acc[2][4][4];
  #pragma unroll
  for(int i=0;i<2;i++)
    #pragma unroll
    for(int j=0;j<4;j++)
      #pragma unroll
      for(int q=0;q<4;q++) acc[i][j][q]=0.f;

  const int arL = (tid>>3);
  const int akL = (tid&7)*4;
  const int bnL = (tid>>2);
  const int bkL = (tid&3)*8;

  float4 pa[4]; uint4 pb;
  const int totalChunks = gd.nterms*16;

  {
    const float* A = Aterm[0];
    #pragma unroll
    for(int it=0;it<4;it++){
      int r = arL + it*32;
      pa[it] = *(const float4*)(A + (size_t)(rowBase+r)*512 + akL);
      if(A2base){
        float4 u = *(const float4*)(A2base + (size_t)(rowBase+r)*512 + akL);
        pa[it].x*=u.x; pa[it].y*=u.y; pa[it].z*=u.z; pa[it].w*=u.w;
      }
    }
    pb = *(const uint4*)(Wp[0] + (size_t)(colBase+bnL)*512 + bkL);
  }
  {
    __half* Ah = sm;
    __half* Bh = sm + PART_A;
    #pragma unroll
    for(int it=0;it<4;it++){
      int r = arL + it*32;
      union { __half b[4]; uint2 u; } ph;
      ph.b[0]=__float2half_rn(pa[it].x); ph.b[1]=__float2half_rn(pa[it].y);
      ph.b[2]=__float2half_rn(pa[it].z); ph.b[3]=__float2half_rn(pa[it].w);
      *(uint2*)(Ah + r*SMS + akL) = ph.u;
    }
    *(uint2*)(Bh + bnL*SMS + bkL)     = make_uint2(pb.x, pb.y);
    *(uint2*)(Bh + bnL*SMS + bkL + 4) = make_uint2(pb.z, pb.w);
  }
  __syncthreads();

  const uint32_t smemBase = (uint32_t)__cvta_generic_to_shared(sm);
  int buf = 0;
  for(int ch=1; ch<=totalChunks; ch++){
    if(ch<totalChunks){
      int term = ch>>4; int k0 = (ch&15)*32;
      const float* A = Aterm[term];
      #pragma unroll
      for(int it=0;it<4;it++){
        int r = arL + it*32;
        pa[it] = *(const float4*)(A + (size_t)(rowBase+r)*512 + k0 + akL);
        if(A2base){
          float4 u = *(const float4*)(A2base + (size_t)(rowBase+r)*512 + k0 + akL);
          pa[it].x*=u.x; pa[it].y*=u.y; pa[it].z*=u.z; pa[it].w*=u.w;
        }
      }
      pb = *(const uint4*)(Wp[term] + (size_t)(colBase+bnL)*512 + k0 + bkL);
    }
    {
      uint32_t aH = smemBase + (uint32_t)(buf*STG)*2;
      uint32_t bH = aH + (uint32_t)PART_A*2;
      #pragma unroll
      for(int kk=0;kk<32;kk+=16){
        uint32_t bh0[4],bh1[4];
        #pragma unroll
        for(int pr=0; pr<2; pr++){
          int n = wc*32 + pr*16 + ((mi>>1)<<3) + wi;
          uint32_t off = (uint32_t)(n*SMS + kk + ((mi&1)<<3))*2;
          uint32_t r0,r1,r2,r3;
          ldsm4(r0,r1,r2,r3, bH + off);
          bh0[2*pr]=r0; bh1[2*pr]=r1; bh0[2*pr+1]=r2; bh1[2*pr+1]=r3;
        }
        #pragma unroll
        for(int mb=0;mb<2;mb++){
          int row = wr*32 + mb*16 + ((mi&1)<<3) + wi;
          uint32_t off = (uint32_t)(row*SMS + kk + ((mi>>1)<<3))*2;
          uint32_t ah0,ah1,ah2,ah3;
          ldsm4(ah0,ah1,ah2,ah3, aH + off);
          #pragma unroll
          for(int nb=0;nb<4;nb++){
            mma16816h(acc[mb][nb], ah0,ah1,ah2,ah3, bh0[nb],bh1[nb]);
          }
        }
      }
    }
    if(ch<totalChunks){
      int nb2 = buf^1;
      __half* Ah = sm + nb2*STG;
      __half* Bh = Ah + PART_A;
      #pragma unroll
      for(int it=0;it<4;it++){
        int r = arL + it*32;
        union { __half b[4]; uint2 u; } ph;
        ph.b[0]=__float2half_rn(pa[it].x); ph.b[1]=__float2half_rn(pa[it].y);
        ph.b[2]=__float2half_rn(pa[it].z); ph.b[3]=__float2half_rn(pa[it].w);
        *(uint2*)(Ah + r*SMS + akL) = ph.u;
      }
      *(uint2*)(Bh + bnL*SMS + bkL)     = make_uint2(pb.x, pb.y);
      *(uint2*)(Bh + bnL*SMS + bkL + 4) = make_uint2(pb.z, pb.w);
      __syncthreads();
      buf = nb2;
    }
  }

  // ---- epilogue
  const float* bias = nullptr;
  if(gd.bKind==0)      bias = edge_b + (size_t)gd.bIdx*512;
  else if(gd.bKind==1) bias = node_b + (size_t)gd.bIdx*512;
  const float* res = (gd.resBuf>=0)? bufPtrC(gd.resBuf,inpute,inputo) : nullptr;
  float* dst = bufPtrM(gd.dstBuf);
  #pragma unroll
  for(int mb=0;mb<2;mb++){
    #pragma unroll
    for(int nb=0;nb<4;nb++){
      int row0 = rowBase + wr*32 + mb*16 + g8;
      int col0 = colBase + wc*32 + nb*8 + tg*2;
      #pragma unroll
      for(int half=0; half<2; half++){
        int row = row0 + half*8;
        float z0 = acc[mb][nb][half*2+0] + (bias? bias[col0]:0.f);
        float z1 = acc[mb][nb][half*2+1] + (bias? bias[col0+1]:0.f);
        if(gd.actCode==1){ z0=fmaxf(z0,0.f); z1=fmaxf(z1,0.f); }
        else if(gd.actCode==2){ z0=geluf(z0); z1=geluf(z1); }
        if(res){
          float2 rv = *(const float2*)(res + (size_t)row*512 + col0);
          z0 += rv.x; z1 += rv.y;
        }
        float2 ov; ov.x = gd.scale*z0; ov.y = gd.scale*z1;
        *(float2*)(dst + (size_t)row*512 + col0) = ov;
      }
    }
  }
}

// ---------------- tensor-core flash attention (R8 bf16 hi/lo split, verbatim) ----------------
#define ASROW 72
#define AQ_H 0
#define AQ_L 9216
#define AK_H 18432
#define AK_L 23040
#define AV_H 27648
#define AV_L 32256
#define ATTN_SMEM_ELEMS 36864

__device__ __forceinline__ void ldsm4t(uint32_t& r0,uint32_t& r1,uint32_t& r2,uint32_t& r3, uint32_t saddr){
  asm volatile("ldmatrix.sync.aligned.m8n8.x4.trans.shared.b16 {%0,%1,%2,%3}, [%4];"
    : "=r"(r0),"=r"(r1),"=r"(r2),"=r"(r3) : "r"(saddr));
}
__device__ __forceinline__ void split2(float a, float b, uint32_t& hi, uint32_t& lo){
  __nv_bfloat16 ha=__float2bfloat16(a), hb=__float2bfloat16(b);
  __nv_bfloat162 hh; hh.x=ha; hh.y=hb; hi = *(uint32_t*)&hh;
  __nv_bfloat162 ll; ll.x=__float2bfloat16(a-__bfloat162float(ha));
  ll.y=__float2bfloat16(b-__bfloat162float(hb)); lo = *(uint32_t*)&ll;
}

__global__ void __launch_bounds__(256,1) attn_kernel(int c){
  if(g_node_act[c]!=0) return;
  extern __shared__ __nv_bfloat16 asm_[];
  const int tid = threadIdx.x;
  const int lane = tid & 31;
  const int wid = tid >> 5;
  const int mi = lane>>3, wi = lane&7;
  const int g8 = lane>>2, tg = lane&3;
  const int bh = blockIdx.y; const int b = bh>>3, h = bh&7;
  const int q0 = blockIdx.x*128;
  const float* Q = g_tt[0]; const float* K = g_tt[1]; const float* V = g_tt[2];
  const uint32_t smemBase = (uint32_t)__cvta_generic_to_shared(asm_);

  {
    int row = tid>>1;
    int col0 = (tid&1)*32;
    const float* src = Q + ((size_t)(b*1024+q0+row))*DIM + h*64 + col0;
    #pragma unroll
    for(int j=0;j<8;j++){
      float4 v = *(const float4*)(src + j*4);
      uint32_t h0,l0,h1,l1;
      split2(v.x,v.y,h0,l0); split2(v.z,v.w,h1,l1);
      int o = row*ASROW + col0 + j*4;
      *(uint32_t*)(asm_+AQ_H+o)   = h0; *(uint32_t*)(asm_+AQ_H+o+2) = h1;
      *(uint32_t*)(asm_+AQ_L+o)   = l0; *(uint32_t*)(asm_+AQ_L+o+2) = l1;
    }
  }
  __syncthreads();

  uint32_t qh[4][4], ql[4][4];
  {
    int row = wid*16 + ((mi&1)<<3) + wi;
    #pragma unroll
    for(int ks=0;ks<4;ks++){
      uint32_t off = (uint32_t)(row*ASROW + ks*16 + ((mi>>1)<<3))*2;
      ldsm4(qh[ks][0],qh[ks][1],qh[ks][2],qh[ks][3], smemBase + AQ_H*2 + off);
      ldsm4(ql[ks][0],ql[ks][1],ql[ks][2],ql[ks][3], smemBase + AQ_L*2 + off);
    }
  }

  float o_acc[8][4];
  #pragma unroll
  for(int nb=0;nb<8;nb++)
    #pragma unroll
    for(int q=0;q<4;q++) o_acc[nb][q]=0.f;
  float m_st[2] = {-1e30f,-1e30f};
  float l_st[2] = {0.f,0.f};

  for(int chunk=0; chunk<16; chunk++){
    __syncthreads();
    {
      int key = tid>>2;
      int col0 = (tid&3)*16;
      size_t base = ((size_t)(b*1024 + chunk*64 + key))*DIM + h*64 + col0;
      #pragma unroll
      for(int j=0;j<4;j++){
        float4 kv = *(const float4*)(K + base + j*4);
        float4 vv = *(const float4*)(V + base + j*4);
        uint32_t h0,l0,h1,l1;
        int o = key*ASROW + col0 + j*4;
        split2(kv.x,kv.y,h0,l0); split2(kv.z,kv.w,h1,l1);
        *(uint32_t*)(asm_+AK_H+o) = h0; *(uint32_t*)(asm_+AK_H+o+2) = h1;
        *(uint32_t*)(asm_+AK_L+o) = l0; *(uint32_t*)(asm_+AK_L+o+2) = l1;
        split2(vv.x,vv.y,h0,l0); split2(vv.z,vv.w,h1,l1);
        *(uint32_t*)(asm_+AV_H+o) = h0; *(uint32_t*)(asm_+AV_H+o+2) = h1;
        *(uint32_t*)(asm_+AV_L+o) = l0; *(uint32_t*)(asm_+AV_L+o+2) = l1;
      }
    }
    __syncthreads();

    float s[8][4];
    #pragma unroll
    for(int nb=0;nb<8;nb++)
      #pragma unroll
      for(int q=0;q<4;q++) s[nb][q]=0.f;
    #pragma unroll
    for(int ks=0;ks<4;ks++){
      uint32_t kb0[8], kb1[8], klo0[8], klo1[8];
      #pragma unroll
      for(int pr=0;pr<4;pr++){
        int n = pr*16 + ((mi>>1)<<3) + wi;
        uint32_t off = (uint32_t)(n*ASROW + ks*16 + ((mi&1)<<3))*2;
        uint32_t r0,r1,r2,r3;
        ldsm4(r0,r1,r2,r3, smemBase + AK_H*2 + off);
        kb0[2*pr]=r0; kb1[2*pr]=r1; kb0[2*pr+1]=r2; kb1[2*pr+1]=r3;
        ldsm4(r0,r1,r2,r3, smemBase + AK_L*2 + off);
        klo0[2*pr]=r0; klo1[2*pr]=r1; klo0[2*pr+1]=r2; klo1[2*pr+1]=r3;
      }
      #pragma unroll
      for(int nb=0;nb<8;nb++){
        mma16816(s[nb], qh[ks][0],qh[ks][1],qh[ks][2],qh[ks][3], kb0[nb],kb1[nb]);
        mma16816(s[nb], qh[ks][0],qh[ks][1],qh[ks][2],qh[ks][3], klo0[nb],klo1[nb]);
        mma16816(s[nb], ql[ks][0],ql[ks][1],ql[ks][2],ql[ks][3], kb0[nb],kb1[nb]);
      }
    }

    float p[8][4];
    #pragma unroll
    for(int hr=0;hr<2;hr++){
      float mloc = -1e30f;
      #pragma unroll
      for(int nb=0;nb<8;nb++){
        float a = s[nb][hr*2+0]*0.125f, bb = s[nb][hr*2+1]*0.125f;
        s[nb][hr*2+0]=a; s[nb][hr*2+1]=bb;
        mloc = fmaxf(mloc, fmaxf(a,bb));
      }
      mloc = fmaxf(mloc, __shfl_xor_sync(0xffffffffu, mloc, 1));
      mloc = fmaxf(mloc, __shfl_xor_sync(0xffffffffu, mloc, 2));
      float m_new = fmaxf(m_st[hr], mloc);
      float corr = __expf(m_st[hr]-m_new);
      float lloc = 0.f;
      #pragma unroll
      for(int nb=0;nb<8;nb++){
        float p0 = __expf(s[nb][hr*2+0]-m_new);
        float p1 = __expf(s[nb][hr*2+1]-m_new);
        p[nb][hr*2+0]=p0; p[nb][hr*2+1]=p1;
        lloc += p0+p1;
      }
      lloc += __shfl_xor_sync(0xffffffffu, lloc, 1);
      lloc += __shfl_xor_sync(0xffffffffu, lloc, 2);
      l_st[hr] = l_st[hr]*corr + lloc;
      m_st[hr] = m_new;
      #pragma unroll
      for(int nb=0;nb<8;nb++){ o_acc[nb][hr*2+0]*=corr; o_acc[nb][hr*2+1]*=corr; }
    }

    #pragma unroll
    for(int ks=0;ks<4;ks++){
      uint32_t pa0,pa1,pa2,pa3, pl0,pl1,pl2,pl3;
      split2(p[2*ks][0],   p[2*ks][1],   pa0, pl0);
      split2(p[2*ks][2],   p[2*ks][3],   pa1, pl1);
      split2(p[2*ks+1][0], p[2*ks+1][1], pa2, pl2);
      split2(p[2*ks+1][2], p[2*ks+1][3], pa3, pl3);
      #pragma unroll
      for(int pr=0;pr<4;pr++){
        int key = ks*16 + ((mi&1)<<3) + wi;
        int d0  = pr*16 + ((mi>>1)<<3);
        uint32_t off = (uint32_t)(key*ASROW + d0)*2;
        uint32_t vh0,vh1,vh2,vh3, vl0,vl1,vl2,vl3;
        ldsm4t(vh0,vh1,vh2,vh3, smemBase + AV_H*2 + off);
        ldsm4t(vl0,vl1,vl2,vl3, smemBase + AV_L*2 + off);
        mma16816(o_acc[2*pr],   pa0,pa1,pa2,pa3, vh0,vh1);
        mma16816(o_acc[2*pr],   pa0,pa1,pa2,pa3, vl0,vl1);
        mma16816(o_acc[2*pr],   pl0,pl1,pl2,pl3, vh0,vh1);
        mma16816(o_acc[2*pr+1], pa0,pa1,pa2,pa3, vh2,vh3);
        mma16816(o_acc[2*pr+1], pa0,pa1,pa2,pa3, vl2,vl3);
        mma16816(o_acc[2*pr+1], pl0,pl1,pl2,pl3, vh2,vh3);
      }
    }
  }

  #pragma unroll
  for(int hr=0;hr<2;hr++){
    float inv = 1.f/l_st[hr];
    int row = q0 + wid*16 + hr*8 + g8;
    #pragma unroll
    for(int nb=0;nb<8;nb++){
      int col = h*64 + nb*8 + tg*2;
      float2 ov; ov.x = o_acc[nb][hr*2+0]*inv; ov.y = o_acc[nb][hr*2+1]*inv;
      *(float2*)(g_attn + ((size_t)(b*1024+row))*DIM + col) = ov;
    }
  }
}

// ---------------- elementwise node ops (warp-per-row) ----------------
__global__ void post_elt(int c, const float* __restrict__ node_g, const float* __restrict__ node_beta){
  int act = g_node_act[c];
  if(act==0||act==1||act==3) return;
  float aw = g_node_aw[c];
  int wid = threadIdx.x>>5, lane = threadIdx.x&31;
  int row = blockIdx.x*8 + wid;
  size_t off=(size_t)row*DIM;
  const float* q=g_qkv[0]+off; const float* k=g_qkv[1]+off; const float* v=g_qkv[2]+off;
  float* o = g_outbuf[c]+off;
  if(act==4||act==5||act==6){
    #pragma unroll
    for(int j=0;j<4;j++){
      int col = lane*4 + j*128;
      float4 qv = *(const float4*)(q+col);
      float4 ov;
      if(act==4){
        float4 kv = *(const float4*)(k+col);
        float4 vv = *(const float4*)(v+col);
        ov.x=aw*(qv.x*sigmoidf(kv.x)+vv.x); ov.y=aw*(qv.y*sigmoidf(kv.y)+vv.y);
        ov.z=aw*(qv.z*sigmoidf(kv.z)+vv.z); ov.w=aw*(qv.w*sigmoidf(kv.w)+vv.w);
      } else if(act==5){
        float4 tv = *(const float4*)(g_tt[0]+off+col);
        ov.x=aw*(qv.x+tv.x); ov.y=aw*(qv.y+tv.y); ov.z=aw*(qv.z+tv.z); ov.w=aw*(qv.w+tv.w);
      } else {
        float4 kv = *(const float4*)(k+col);
        ov.x=aw*(qv.x+kv.x); ov.y=aw*(qv.y+kv.y); ov.z=aw*(qv.z+kv.z); ov.w=aw*(qv.w+kv.w);
      }
      *(float4*)(o+col)=ov;
    }
    return;
  }
  float4 x[4];
  #pragma unroll
  for(int j=0;j<4;j++){
    int col = lane*4 + j*128;
    float4 qv = *(const float4*)(q+col);
    if(act==2){
      float4 kv = *(const float4*)(k+col);
      float4 vv = *(const float4*)(v+col);
      qv.x+=kv.x+vv.x; qv.y+=kv.y+vv.y; qv.z+=kv.z+vv.z; qv.w+=kv.w+vv.w;
    }
    x[j]=qv;
  }
  float s=0.f;
  #pragma unroll
  for(int j=0;j<4;j++) s += x[j].x+x[j].y+x[j].z+x[j].w;
  float mean = warpReduceSum(s)*(1.f/512.f);
  float s2=0.f;
  #pragma unroll
  for(int j=0;j<4;j++){
    float a=x[j].x-mean,b=x[j].y-mean,cc=x[j].z-mean,dd=x[j].w-mean;
    s2 += a*a+b*b+cc*cc+dd*dd;
  }
  float rstd = rsqrtf(warpReduceSum(s2)*(1.f/512.f)+1e-6f);
  const float* g  = node_g    + (size_t)c*DIM;
  const float* be = node_beta + (size_t)c*DIM;
  #pragma unroll
  for(int j=0;j<4;j++){
    int col = lane*4 + j*128;
    float4 gv = *(const float4*)(g+col);
    float4 bv = *(const float4*)(be+col);
    float4 ov;
    ov.x=aw*((x[j].x-mean)*rstd*gv.x+bv.x); ov.y=aw*((x[j].y-mean)*rstd*gv.y+bv.y);
    ov.z=aw*((x[j].z-mean)*rstd*gv.z+bv.z); ov.w=aw*((x[j].w-mean)*rstd*gv.w+bv.w);
    *(float4*)(o+col)=ov;
  }
}

// ---------------- final: sum remaining nodes + LN (warp-per-row) ----------------
__global__ void final_kernel(const float* __restrict__ og, const float* __restrict__ obe, float* __restrict__ out){
  int wid = threadIdx.x>>5, lane = threadIdx.x&31;
  int row = blockIdx.x*8 + wid;
  int mask = g_rem_mask;
  size_t off=(size_t)row*DIM;
  float4 x[4];
  #pragma unroll
  for(int j=0;j<4;j++){ x[j].x=0;x[j].y=0;x[j].z=0;x[j].w=0; }
  #pragma unroll
  for(int i=0;i<8;i++) if((mask>>i)&1){
    #pragma unroll
    for(int j=0;j<4;j++){
      float4 v = *(const float4*)(g_outbuf[i]+off+lane*4+j*128);
      x[j].x+=v.x; x[j].y+=v.y; x[j].z+=v.z; x[j].w+=v.w;
    }
  }
  float s=0.f;
  #pragma unroll
  for(int j=0;j<4;j++) s += x[j].x+x[j].y+x[j].z+x[j].w;
  float mean = warpReduceSum(s)*(1.f/512.f);
  float s2=0.f;
  #pragma unroll
  for(int j=0;j<4;j++){
    float a=x[j].x-mean,b=x[j].y-mean,cc=x[j].z-mean,dd=x[j].w-mean;
    s2 += a*a+b*b+cc*cc+dd*dd;
  }
  float rstd = rsqrtf(warpReduceSum(s2)*(1.f/512.f)+1e-6f);
  #pragma unroll
  for(int j=0;j<4;j++){
    int col = lane*4 + j*128;
    float4 gv = *(const float4*)(og+col);
    float4 bv = *(const float4*)(obe+col);
    float4 ov;
    ov.x=(x[j].x-mean)*rstd*gv.x+bv.x; ov.y=(x[j].y-mean)*rstd*gv.y+bv.y;
    ov.z=(x[j].z-mean)*rstd*gv.z+bv.z; ov.w=(x[j].w-mean)*rstd*gv.w+bv.w;
    *(float4*)(out+off+col)=ov;
  }
}

extern "C" void kernel_launch(void* const* d_in, const int* in_sizes, int n_in,
                              void* d_out, int out_size) {
  (void)in_sizes; (void)n_in; (void)out_size;
  const float* inpute    = (const float*)d_in[0];
  const float* inputo    = (const float*)d_in[1];
  const float* node_p    = (const float*)d_in[2];
  const float* edge_p    = (const float*)d_in[3];
  const float* edge_W    = (const float*)d_in[4];
  const float* edge_b    = (const float*)d_in[5];
  const float* edge_g    = (const float*)d_in[6];
  const float* edge_beta = (const float*)d_in[7];
  const float* node_W    = (const float*)d_in[8];
  const float* node_b    = (const float*)d_in[9];
  const float* node_g    = (const float*)d_in[10];
  const float* node_beta = (const float*)d_in[11];
  const float* out_g     = (const float*)d_in[12];
  const float* out_beta  = (const float*)d_in[13];
  float* out = (float*)d_out;

  const int gemmSmem = 2*STG*(int)sizeof(__half); // 30720 bytes
  cudaFuncSetAttribute(gemm_kernel, cudaFuncAttributeMaxDynamicSharedMemorySize, gemmSmem);
  const int attnSmem = ATTN_SMEM_ELEMS*(int)sizeof(__nv_bfloat16); // 73728 bytes
  cudaFuncSetAttribute(attn_kernel, cudaFuncAttributeMaxDynamicSharedMemorySize, attnSmem);

  route_kernel<<<1,1>>>(node_p, edge_p);
  convw_kernel<<<dim3(16,16,66),256>>>(edge_W, node_W);
  for(int c=0;c<8;c++){
    prep_kernel<<<dim3(512,1,3),256>>>(c, inpute, inputo, edge_g, edge_beta);
    gemm_kernel<<<dim3(8,32,3),256,gemmSmem>>>(c,0,inpute,inputo,edge_b,node_b);
    lnq_kernel<<<512,256>>>(c, node_g, node_beta);
    gemm_kernel<<<dim3(8,32,3),256,gemmSmem>>>(c,3,inpute,inputo,edge_b,node_b);
    attn_kernel<<<dim3(8,32),256,attnSmem>>>(c);
    gemm_kernel<<<dim3(8,32,1),256,gemmSmem>>>(c,6,inpute,inputo,edge_b,node_b);
    post_elt<<<512,256>>>(c, node_g, node_beta);
  }
  final_kernel<<<512,256>>>(out_g, out_beta, out);
}